// round 10
// baseline (speedup 1.0000x reference)
#include <cuda_runtime.h>
#include <cuda_fp16.h>
#include <math.h>

#define NE_MAX 200000
#define NA_MAX 1600000
#define ATILE 32
#define SCAN_BLOCKS 256

// ---- static scratch ----
__device__ __half g_P0h[(size_t)NE_MAX * 128];
__device__ __half g_P1h[(size_t)NE_MAX * 128];
__device__ __half g_gbufh[(size_t)NA_MAX * 128];
__device__ float g_csum[256 * 128];
__device__ float g_csumsq[256 * 128];
__device__ unsigned g_ccnt[256];
__device__ float g_a1[256 * 128];
__device__ float g_b1[256 * 128];
__device__ float g_summed[(size_t)NE_MAX * 64];
__device__ unsigned g_acnt[NE_MAX];
__device__ unsigned g_off[NE_MAX + 1];
__device__ unsigned g_curs[NE_MAX];
__device__ int g_bucket[NA_MAX];
__device__ unsigned g_blksum[SCAN_BLOCKS];
__device__ unsigned g_blkoff[SCAN_BLOCKS];
__device__ float g_esum[256 * 64];
__device__ float g_esumsq[256 * 64];
__device__ unsigned g_ecnt[256];
__device__ float g_a2[256 * 64];
__device__ float g_b2[256 * 64];

typedef unsigned long long ull;
__device__ __forceinline__ ull ffma2(ull a, ull b, ull c) {
    ull d; asm("fma.rn.f32x2 %0, %1, %2, %3;" : "=l"(d) : "l"(a), "l"(b), "l"(c)); return d;
}
__device__ __forceinline__ ull pack2(float x, float y) {
    ull d; asm("mov.b64 %0, {%1, %2};" : "=l"(d) : "f"(x), "f"(y)); return d;
}
__device__ __forceinline__ float2 unpack2(ull a) {
    float x, y; asm("mov.b64 {%0, %1}, %2;" : "=f"(x), "=f"(y) : "l"(a));
    return make_float2(x, y);
}
__device__ __forceinline__ float4 ld_half4(const __half* p) {
    uint2 u = *(const uint2*)p;
    float2 fa = __half22float2(*(__half2*)&u.x);
    float2 fb = __half22float2(*(__half2*)&u.y);
    return make_float4(fa.x, fa.y, fb.x, fb.y);
}
__device__ __forceinline__ void cp_async8(void* smem, const void* gmem) {
    unsigned s = (unsigned)__cvta_generic_to_shared(smem);
    asm volatile("cp.async.ca.shared.global [%0], [%1], 8;" :: "r"(s), "l"(gmem));
}
__device__ __forceinline__ void cp_async4(void* smem, const void* gmem) {
    unsigned s = (unsigned)__cvta_generic_to_shared(smem);
    asm volatile("cp.async.ca.shared.global [%0], [%1], 4;" :: "r"(s), "l"(gmem));
}
__device__ __forceinline__ void cp_commit() { asm volatile("cp.async.commit_group;" ::: "memory"); }
template <int N>
__device__ __forceinline__ void cp_wait() { asm volatile("cp.async.wait_group %0;" :: "n"(N) : "memory"); }
__device__ __forceinline__ void mma_16816(float c[4], unsigned a0, unsigned a1,
                                          unsigned a2, unsigned a3,
                                          unsigned b0, unsigned b1) {
    asm volatile(
        "mma.sync.aligned.m16n8k16.row.col.f32.f16.f16.f32 "
        "{%0,%1,%2,%3}, {%4,%5,%6,%7}, {%8,%9}, {%0,%1,%2,%3};"
        : "+f"(c[0]), "+f"(c[1]), "+f"(c[2]), "+f"(c[3])
        : "r"(a0), "r"(a1), "r"(a2), "r"(a3), "r"(b0), "r"(b1));
}

// ---- K0: zero accumulators ----
__global__ void k_zero(int n_edges) {
    int i = blockIdx.x * blockDim.x + threadIdx.x;
    int stride = gridDim.x * blockDim.x;
    for (int k = i; k < n_edges; k += stride) g_acnt[k] = 0u;
    for (int k = i; k < 256 * 128; k += stride) { g_csum[k] = 0.f; g_csumsq[k] = 0.f; }
    for (int k = i; k < 256 * 64; k += stride) { g_esum[k] = 0.f; g_esumsq[k] = 0.f; }
    for (int k = i; k < 256; k += stride) { g_ccnt[k] = 0u; g_ecnt[k] = 0u; }
}

// ---- K1: P0/P1 = nbr_fea @ W_full halves (fp16 out, k-packed FFMA2) ----
__global__ void __launch_bounds__(128) k_precompute(
        const float* __restrict__ nbr, const float* __restrict__ W_full, int n_edges) {
    int j = threadIdx.x;
    int half = blockIdx.y;
    ull w2[32];
    const float* wb = W_full + (size_t)(40 + half * 64) * 128 + j;
#pragma unroll
    for (int kk = 0; kk < 32; kk++)
        w2[kk] = pack2(wb[(size_t)(2 * kk) * 128], wb[(size_t)(2 * kk + 1) * 128]);
    __half* P = half ? g_P1h : g_P0h;
    __shared__ __align__(16) ull snb[2][32];
    int nb = gridDim.x;
    for (int e2 = blockIdx.x * 2; e2 < n_edges; e2 += nb * 2) {
        if (j < 64) {
            int g = j >> 5, jj = j & 31;
            int e = min(e2 + g, n_edges - 1);
            snb[g][jj] = ((const ull*)(nbr + (size_t)e * 64))[jj];
        }
        __syncthreads();
#pragma unroll 2
        for (int gg = 0; gg < 2; gg++) {
            int ee = e2 + gg;
            if (ee >= n_edges) break;
            ull acc = 0ull;
#pragma unroll
            for (int kk = 0; kk < 16; kk++) {
                ulonglong2 v = *(const ulonglong2*)&snb[gg][2 * kk];
                acc = ffma2(v.x, w2[2 * kk], acc);
                acc = ffma2(v.y, w2[2 * kk + 1], acc);
            }
            float2 u = unpack2(acc);
            P[(size_t)ee * 128 + j] = __float2half_rn(u.x + u.y);
        }
        __syncthreads();
    }
}

// ---- K2: count angles per src edge ----
__global__ void k_count(const int* __restrict__ anb, int n_angles) {
    int i = blockIdx.x * blockDim.x + threadIdx.x;
    if (i < n_angles) atomicAdd(&g_acnt[anb[2 * (size_t)i]], 1u);
}

// ---- K3: angle GEMM via HMMA + inline crystal stats (smem x tile). ----
__global__ void __launch_bounds__(128) k_angle_mma(
        const float* __restrict__ af, const int* __restrict__ anb,
        const int* __restrict__ ca, const float* __restrict__ W,
        int n_angles, int chunk) {
    int tid = threadIdx.x;
    int wid = tid >> 5, lane = tid & 31;
    int g = lane >> 2, t = lane & 3;
    int nbase = wid * 32;

    unsigned bfrag[4][3][2];
#pragma unroll
    for (int nt = 0; nt < 4; nt++)
#pragma unroll
        for (int ks = 0; ks < 3; ks++) {
            int ch = nbase + nt * 8 + g;
            int k0 = ks * 16 + 2 * t;
            float w00 = (k0 < 40)     ? __ldg(&W[(size_t)k0 * 128 + ch]) : 0.f;
            float w01 = (k0 + 1 < 40) ? __ldg(&W[(size_t)(k0 + 1) * 128 + ch]) : 0.f;
            float w10 = (k0 + 8 < 40) ? __ldg(&W[(size_t)(k0 + 8) * 128 + ch]) : 0.f;
            float w11 = (k0 + 9 < 40) ? __ldg(&W[(size_t)(k0 + 9) * 128 + ch]) : 0.f;
            __half2 h0 = __floats2half2_rn(w00, w01);
            __half2 h1 = __floats2half2_rn(w10, w11);
            bfrag[nt][ks][0] = *(unsigned*)&h0;
            bfrag[nt][ks][1] = *(unsigned*)&h1;
        }

    __shared__ __align__(16) ull s_af[2][ATILE * 20];
    __shared__ int s_ii[2][ATILE * 2];
    __shared__ int s_ca[2][ATILE];
    __shared__ __align__(16) __half sAh[32][56];
    __shared__ __half sX[32][136];     // x values for stats pass (pad: conflict-free)

    for (int idx = tid; idx < 32 * 16; idx += 128)
        sAh[idx >> 4][40 + (idx & 15)] = __float2half(0.f);

    int a0 = blockIdx.x * chunk;
    int aend = min(a0 + chunk, n_angles);
    if (a0 >= aend) return;

    const ull* af2 = (const ull*)af;
    int maxf2 = n_angles * 20 - 1;
    int maxi  = n_angles - 1;

    {
#pragma unroll
        for (int r = 0; r < 5; r++) {
            int pos = r * 128 + tid;
            cp_async8(&s_af[0][pos], &af2[min(a0 * 20 + pos, maxf2)]);
        }
        if (tid < 64) cp_async4(&s_ii[0][tid], &anb[min(2 * a0 + tid, 2 * maxi + 1)]);
        else if (tid < 96) cp_async4(&s_ca[0][tid - 64], &ca[min(a0 + tid - 64, maxi)]);
        cp_commit();
    }

    float lsum = 0.f, lsq = 0.f;
    int lcnt = 0;
    int curc = __ldg(&ca[a0]);

    int buf = 0;
    for (int base = a0; base < aend; base += ATILE, buf ^= 1) {
        int nb = min(ATILE, aend - base);
        int nbase2 = base + ATILE;
        bool has_next = nbase2 < aend;
        if (has_next) {
#pragma unroll
            for (int r = 0; r < 5; r++) {
                int pos = r * 128 + tid;
                cp_async8(&s_af[buf ^ 1][pos], &af2[min(nbase2 * 20 + pos, maxf2)]);
            }
            if (tid < 64) cp_async4(&s_ii[buf ^ 1][tid], &anb[min(2 * nbase2 + tid, 2 * maxi + 1)]);
            else if (tid < 96) cp_async4(&s_ca[buf ^ 1][tid - 64], &ca[min(nbase2 + tid - 64, maxi)]);
            cp_commit();
            cp_wait<1>();
        } else {
            cp_wait<0>();
        }
        __syncthreads();
        const float* afv = (const float*)s_af[buf];
#pragma unroll
        for (int q = 0; q < 10; q++) {
            int idx = q * 128 + tid;
            sAh[idx / 40][idx % 40] = __float2half_rn(afv[idx]);
        }
        __syncthreads();

#pragma unroll
        for (int mt = 0; mt < 2; mt++) {
            int rA = mt * 16 + g;
            int rB = rA + 8;
            int i0A = s_ii[buf][2 * rA], i1A = s_ii[buf][2 * rA + 1];
            int i0B = s_ii[buf][2 * rB], i1B = s_ii[buf][2 * rB + 1];
            unsigned p0A[4], p1A[4], p0B[4], p1B[4];
#pragma unroll
            for (int nt = 0; nt < 4; nt++) {
                int ch = nbase + nt * 8 + 2 * t;
                p0A[nt] = *(const unsigned*)&g_P0h[(size_t)i0A * 128 + ch];
                p1A[nt] = *(const unsigned*)&g_P1h[(size_t)i1A * 128 + ch];
                p0B[nt] = *(const unsigned*)&g_P0h[(size_t)i0B * 128 + ch];
                p1B[nt] = *(const unsigned*)&g_P1h[(size_t)i1B * 128 + ch];
            }
            float c[4][4];
#pragma unroll
            for (int nt = 0; nt < 4; nt++)
#pragma unroll
                for (int q = 0; q < 4; q++) c[nt][q] = 0.f;
#pragma unroll
            for (int ks = 0; ks < 3; ks++) {
                unsigned a0f = *(const unsigned*)&sAh[rA][ks * 16 + 2 * t];
                unsigned a1f = *(const unsigned*)&sAh[rB][ks * 16 + 2 * t];
                unsigned a2f = *(const unsigned*)&sAh[rA][ks * 16 + 2 * t + 8];
                unsigned a3f = *(const unsigned*)&sAh[rB][ks * 16 + 2 * t + 8];
#pragma unroll
                for (int nt = 0; nt < 4; nt++)
                    mma_16816(c[nt], a0f, a1f, a2f, a3f,
                              bfrag[nt][ks][0], bfrag[nt][ks][1]);
            }
            int angleA = base + rA;
            int angleB = base + rB;
#pragma unroll
            for (int nt = 0; nt < 4; nt++) {
                int ch = nbase + nt * 8 + 2 * t;
                if (angleA < aend) {
                    float2 q0 = __half22float2(*(__half2*)&p0A[nt]);
                    float2 q1 = __half22float2(*(__half2*)&p1A[nt]);
                    __half2 o = __floats2half2_rn(c[nt][0] + q0.x + q1.x,
                                                  c[nt][1] + q0.y + q1.y);
                    *(__half2*)&g_gbufh[(size_t)angleA * 128 + ch] = o;
                    *(__half2*)&sX[rA][ch] = o;
                }
                if (angleB < aend) {
                    float2 q0 = __half22float2(*(__half2*)&p0B[nt]);
                    float2 q1 = __half22float2(*(__half2*)&p1B[nt]);
                    __half2 o = __floats2half2_rn(c[nt][2] + q0.x + q1.x,
                                                  c[nt][3] + q0.y + q1.y);
                    *(__half2*)&g_gbufh[(size_t)angleB * 128 + ch] = o;
                    *(__half2*)&sX[rB][ch] = o;
                }
            }
        }
        __syncthreads();
        // ---- stats pass: thread owns channel tid, walks tile rows ----
        for (int r = 0; r < nb; r++) {
            int c = s_ca[buf][r];
            if (c != curc) {
                atomicAdd(&g_csum[curc * 128 + tid], lsum);
                atomicAdd(&g_csumsq[curc * 128 + tid], lsq);
                if (tid == 0) atomicAdd(&g_ccnt[curc], (unsigned)lcnt);
                lsum = 0.f; lsq = 0.f; lcnt = 0; curc = c;
            }
            float x = __half2float(sX[r][tid]);
            lsum += x; lsq = fmaf(x, x, lsq); lcnt++;
        }
        __syncthreads();
    }
    atomicAdd(&g_csum[curc * 128 + tid], lsum);
    atomicAdd(&g_csumsq[curc * 128 + tid], lsq);
    if (tid == 0) atomicAdd(&g_ccnt[curc], (unsigned)lcnt);
}

// ---- K4: finalize crystal_norm1 affine ----
__global__ void k_stats1(const float* __restrict__ gn1_g, const float* __restrict__ gn1_b) {
    int c = blockIdx.x, j = threadIdx.x;
    float cnt = fmaxf((float)g_ccnt[c], 1.f);
    float mean = g_csum[c * 128 + j] / cnt;
    float var = fmaxf(g_csumsq[c * 128 + j] / cnt - mean * mean, 0.f);
    float inv = rsqrtf(var + 1e-5f);
    float a = gn1_g[j] * inv;
    g_a1[c * 128 + j] = a;
    g_b1[c * 128 + j] = gn1_b[j] - mean * a;
}

// ---- K5a/b/c: parallel exclusive scan over counts ----
__global__ void k_scanA(int n_edges) {
    __shared__ unsigned sred[256];
    int b = blockIdx.x, t = threadIdx.x;
    int per = (n_edges + SCAN_BLOCKS - 1) / SCAN_BLOCKS;
    int s = b * per, e = min(s + per, n_edges);
    unsigned local = 0;
    for (int i = s + t; i < e; i += 256) local += g_acnt[i];
    sred[t] = local;
    __syncthreads();
    for (int off = 128; off; off >>= 1) {
        if (t < off) sred[t] += sred[t + off];
        __syncthreads();
    }
    if (t == 0) g_blksum[b] = sred[0];
}
__global__ void k_scanB(int n_edges) {
    __shared__ unsigned ss[SCAN_BLOCKS];
    int t = threadIdx.x;
    ss[t] = g_blksum[t];
    __syncthreads();
    for (int off = 1; off < SCAN_BLOCKS; off <<= 1) {
        unsigned v = (t >= off) ? ss[t - off] : 0u;
        __syncthreads();
        if (t >= off) ss[t] += v;
        __syncthreads();
    }
    g_blkoff[t] = ss[t] - g_blksum[t];
    if (t == SCAN_BLOCKS - 1) g_off[n_edges] = ss[t];
}
__global__ void k_scanC(int n_edges) {
    __shared__ unsigned ss[256];
    int b = blockIdx.x, t = threadIdx.x;
    int per = (n_edges + SCAN_BLOCKS - 1) / SCAN_BLOCKS;
    int s0 = b * per, e0 = min(s0 + per, n_edges);
    int per2 = (per + 255) / 256;
    int s = s0 + t * per2, e = min(s + per2, e0);
    unsigned local = 0;
    for (int i = s; i < e; i++) local += g_acnt[i];
    ss[t] = local;
    __syncthreads();
    for (int off = 1; off < 256; off <<= 1) {
        unsigned v = (t >= off) ? ss[t - off] : 0u;
        __syncthreads();
        if (t >= off) ss[t] += v;
        __syncthreads();
    }
    unsigned run = g_blkoff[b] + ss[t] - local;
    for (int i = s; i < e; i++) {
        unsigned c = g_acnt[i];
        g_off[i] = run;
        g_curs[i] = run;
        run += c;
    }
}

// ---- K6: fill CSR buckets ----
__global__ void k_fill(const int* __restrict__ anb, int n_angles) {
    int i = blockIdx.x * blockDim.x + threadIdx.x;
    if (i < n_angles) {
        int s = anb[2 * (size_t)i];
        unsigned p = atomicAdd(&g_curs[s], 1u);
        g_bucket[p] = i;
    }
}

// ---- K7: fused gate+gather, 4-wide angle unroll for MLP ----
__global__ void __launch_bounds__(256) k_gather(const int* __restrict__ ca,
                                                const int* __restrict__ ce,
                                                const float* __restrict__ W_mask,
                                                int n_edges) {
    int gw = blockIdx.x * (blockDim.x >> 5) + (threadIdx.x >> 5);
    int lane = threadIdx.x & 31;
    int totalw = gridDim.x * (blockDim.x >> 5);
    int chunk = (n_edges + totalw - 1) / totalw;
    int e0 = gw * chunk, eend = min(e0 + chunk, n_edges);
    if (e0 >= eend) return;
    float4 wm = make_float4(0.f, 0.f, 0.f, 0.f);
    if (lane >= 16) wm = ((const float4*)W_mask)[lane - 16];
    float4 lsum = make_float4(0.f, 0.f, 0.f, 0.f);
    float4 lsq  = make_float4(0.f, 0.f, 0.f, 0.f);
    int lcnt = 0;
    int curc = __ldg(&ce[e0]);
    for (int e = e0; e < eend; e++) {
        int c = __ldg(&ce[e]);
        if (c != curc) {
            if (lane < 16) {
                int b = curc * 64 + 4 * lane;
                atomicAdd(&g_esum[b + 0], lsum.x); atomicAdd(&g_esum[b + 1], lsum.y);
                atomicAdd(&g_esum[b + 2], lsum.z); atomicAdd(&g_esum[b + 3], lsum.w);
                atomicAdd(&g_esumsq[b + 0], lsq.x); atomicAdd(&g_esumsq[b + 1], lsq.y);
                atomicAdd(&g_esumsq[b + 2], lsq.z); atomicAdd(&g_esumsq[b + 3], lsq.w);
            }
            if (lane == 0) atomicAdd(&g_ecnt[curc], (unsigned)lcnt);
            lsum = make_float4(0.f, 0.f, 0.f, 0.f);
            lsq = make_float4(0.f, 0.f, 0.f, 0.f);
            lcnt = 0; curc = c;
        }
        unsigned s = g_off[e], t = g_off[e + 1];
        float4 acc = make_float4(0.f, 0.f, 0.f, 0.f);
        for (unsigned p = s; p < t; p += 4) {
            unsigned m = t - p;   // #valid in this group (>=1)
            int aid[4], cc[4];
#pragma unroll
            for (int q = 0; q < 4; q++)
                aid[q] = __ldg(&g_bucket[min(p + q, t - 1)]);
#pragma unroll
            for (int q = 0; q < 4; q++)
                cc[q] = __ldg(&ca[aid[q]]);
            float4 xv[4];
            float part[4];
#pragma unroll
            for (int q = 0; q < 4; q++) {
                float4 g4 = ld_half4(&g_gbufh[(size_t)aid[q] * 128 + 4 * lane]);
                float4 a4 = *(const float4*)&g_a1[cc[q] * 128 + 4 * lane];
                float4 b4 = *(const float4*)&g_b1[cc[q] * 128 + 4 * lane];
                xv[q].x = fmaf(g4.x, a4.x, b4.x);
                xv[q].y = fmaf(g4.y, a4.y, b4.y);
                xv[q].z = fmaf(g4.z, a4.z, b4.z);
                xv[q].w = fmaf(g4.w, a4.w, b4.w);
                part[q] = xv[q].x * wm.x + xv[q].y * wm.y + xv[q].z * wm.z + xv[q].w * wm.w;
            }
#pragma unroll
            for (int o = 16; o; o >>= 1) {
#pragma unroll
                for (int q = 0; q < 4; q++)
                    part[q] += __shfl_xor_sync(0xffffffffu, part[q], o);
            }
#pragma unroll
            for (int q = 0; q < 4; q++) {
                if ((unsigned)q < m) {
                    float f = 1.f - 2.f / (__expf(2.f * part[q]) + 1.f);
                    acc.x += f * fmaxf(xv[q].x, 0.f);
                    acc.y += f * fmaxf(xv[q].y, 0.f);
                    acc.z += f * fmaxf(xv[q].z, 0.f);
                    acc.w += f * fmaxf(xv[q].w, 0.f);
                }
            }
        }
        float inv = 1.f / fmaxf((float)(t - s), 1.f);
        float4 v = make_float4(acc.x * inv, acc.y * inv, acc.z * inv, acc.w * inv);
        if (lane < 16) {
            *(float4*)&g_summed[(size_t)e * 64 + 4 * lane] = v;
            lsum.x += v.x; lsum.y += v.y; lsum.z += v.z; lsum.w += v.w;
            lsq.x += v.x * v.x; lsq.y += v.y * v.y; lsq.z += v.z * v.z; lsq.w += v.w * v.w;
        }
        lcnt++;
    }
    if (lane < 16) {
        int b = curc * 64 + 4 * lane;
        atomicAdd(&g_esum[b + 0], lsum.x); atomicAdd(&g_esum[b + 1], lsum.y);
        atomicAdd(&g_esum[b + 2], lsum.z); atomicAdd(&g_esum[b + 3], lsum.w);
        atomicAdd(&g_esumsq[b + 0], lsq.x); atomicAdd(&g_esumsq[b + 1], lsq.y);
        atomicAdd(&g_esumsq[b + 2], lsq.z); atomicAdd(&g_esumsq[b + 3], lsq.w);
    }
    if (lane == 0) atomicAdd(&g_ecnt[curc], (unsigned)lcnt);
}

// ---- K9: finalize crystal_norm2 affine ----
__global__ void k_stats2(const float* __restrict__ gn2_g, const float* __restrict__ gn2_b) {
    int c = blockIdx.x, j = threadIdx.x;
    float cnt = fmaxf((float)g_ecnt[c], 1.f);
    float mean = g_esum[c * 64 + j] / cnt;
    float var = fmaxf(g_esumsq[c * 64 + j] / cnt - mean * mean, 0.f);
    float inv = rsqrtf(var + 1e-5f);
    float a = gn2_g[j] * inv;
    g_a2[c * 64 + j] = a;
    g_b2[c * 64 + j] = gn2_b[j] - mean * a;
}

// ---- K10: thread-per-edge residual MLPs ----
__global__ void __launch_bounds__(256) k_final(
        const float* __restrict__ nbr, const int* __restrict__ ce,
        const float* __restrict__ W1a, const float* __restrict__ b1a,
        const float* __restrict__ W2a, const float* __restrict__ b2a,
        const float* __restrict__ W1b, const float* __restrict__ b1b,
        const float* __restrict__ W2b, const float* __restrict__ b2b,
        float* __restrict__ out, int n_edges) {
    __shared__ float4 sW1a[512], sW2a[512], sW1b[512], sW2b[512];
    __shared__ float sb1a[32], sb2a[64], sb1b[32], sb2b[64];
    int t = threadIdx.x;
    for (int k = t; k < 512; k += 256) {
        sW1a[k] = ((const float4*)W1a)[k];
        sW2a[k] = ((const float4*)W2a)[k];
        sW1b[k] = ((const float4*)W1b)[k];
        sW2b[k] = ((const float4*)W2b)[k];
    }
    if (t < 32) { sb1a[t] = b1a[t]; sb1b[t] = b1b[t]; }
    if (t < 64) { sb2a[t] = b2a[t]; sb2b[t] = b2b[t]; }
    __syncthreads();
    int e = blockIdx.x * 256 + t;
    if (e >= n_edges) return;

    float h[64];
    int c = __ldg(&ce[e]);
    {
        const float4* s4 = (const float4*)&g_summed[(size_t)e * 64];
        const float4* a4 = (const float4*)&g_a2[c * 64];
        const float4* b4 = (const float4*)&g_b2[c * 64];
#pragma unroll
        for (int i = 0; i < 16; i++) {
            float4 sv = s4[i], av = a4[i], bv = b4[i];
            h[4 * i + 0] = fmaf(sv.x, av.x, bv.x);
            h[4 * i + 1] = fmaf(sv.y, av.y, bv.y);
            h[4 * i + 2] = fmaf(sv.z, av.z, bv.z);
            h[4 * i + 3] = fmaf(sv.w, av.w, bv.w);
        }
    }
    float r[32];
    {
        ull racc[16];
#pragma unroll
        for (int j = 0; j < 16; j++) racc[j] = pack2(sb1a[2 * j], sb1a[2 * j + 1]);
#pragma unroll
        for (int k = 0; k < 64; k++) {
            ull hk = pack2(h[k], h[k]);
#pragma unroll
            for (int j = 0; j < 8; j++) {
                float4 w4 = sW1a[k * 8 + j];
                racc[2 * j]     = ffma2(hk, pack2(w4.x, w4.y), racc[2 * j]);
                racc[2 * j + 1] = ffma2(hk, pack2(w4.z, w4.w), racc[2 * j + 1]);
            }
        }
#pragma unroll
        for (int j = 0; j < 16; j++) {
            float2 u = unpack2(racc[j]);
            r[2 * j] = fmaxf(u.x, 0.f);
            r[2 * j + 1] = fmaxf(u.y, 0.f);
        }
        ull hacc[32];
#pragma unroll
        for (int j = 0; j < 32; j++) hacc[j] = pack2(h[2 * j] + sb2a[2 * j], h[2 * j + 1] + sb2a[2 * j + 1]);
#pragma unroll
        for (int k = 0; k < 32; k++) {
            ull rk = pack2(r[k], r[k]);
#pragma unroll
            for (int j = 0; j < 16; j++) {
                float4 w4 = sW2a[k * 16 + j];
                hacc[2 * j]     = ffma2(rk, pack2(w4.x, w4.y), hacc[2 * j]);
                hacc[2 * j + 1] = ffma2(rk, pack2(w4.z, w4.w), hacc[2 * j + 1]);
            }
        }
#pragma unroll
        for (int j = 0; j < 32; j++) {
            float2 u = unpack2(hacc[j]);
            h[2 * j] = u.x; h[2 * j + 1] = u.y;
        }
    }
    {
        ull racc[16];
#pragma unroll
        for (int j = 0; j < 16; j++) racc[j] = pack2(sb1b[2 * j], sb1b[2 * j + 1]);
#pragma unroll
        for (int k = 0; k < 64; k++) {
            ull hk = pack2(h[k], h[k]);
#pragma unroll
            for (int j = 0; j < 8; j++) {
                float4 w4 = sW1b[k * 8 + j];
                racc[2 * j]     = ffma2(hk, pack2(w4.x, w4.y), racc[2 * j]);
                racc[2 * j + 1] = ffma2(hk, pack2(w4.z, w4.w), racc[2 * j + 1]);
            }
        }
#pragma unroll
        for (int j = 0; j < 16; j++) {
            float2 u = unpack2(racc[j]);
            r[2 * j] = fmaxf(u.x, 0.f);
            r[2 * j + 1] = fmaxf(u.y, 0.f);
        }
        ull hacc[32];
#pragma unroll
        for (int j = 0; j < 32; j++) hacc[j] = pack2(h[2 * j] + sb2b[2 * j], h[2 * j + 1] + sb2b[2 * j + 1]);
#pragma unroll
        for (int k = 0; k < 32; k++) {
            ull rk = pack2(r[k], r[k]);
#pragma unroll
            for (int j = 0; j < 16; j++) {
                float4 w4 = sW2b[k * 16 + j];
                hacc[2 * j]     = ffma2(rk, pack2(w4.x, w4.y), hacc[2 * j]);
                hacc[2 * j + 1] = ffma2(rk, pack2(w4.z, w4.w), hacc[2 * j + 1]);
            }
        }
#pragma unroll
        for (int j = 0; j < 32; j++) {
            float2 u = unpack2(hacc[j]);
            h[2 * j] = u.x; h[2 * j + 1] = u.y;
        }
    }
    {
        const float4* n4 = (const float4*)&nbr[(size_t)e * 64];
        float4* o4 = (float4*)&out[(size_t)e * 64];
#pragma unroll
        for (int i = 0; i < 16; i++) {
            float4 nv = n4[i];
            float4 ov;
            ov.x = 0.7071067811865476f * fmaxf(nv.x + h[4 * i + 0], 0.f);
            ov.y = 0.7071067811865476f * fmaxf(nv.y + h[4 * i + 1], 0.f);
            ov.z = 0.7071067811865476f * fmaxf(nv.z + h[4 * i + 2], 0.f);
            ov.w = 0.7071067811865476f * fmaxf(nv.w + h[4 * i + 3], 0.f);
            o4[i] = ov;
        }
    }
}

extern "C" void kernel_launch(void* const* d_in, const int* in_sizes, int n_in,
                              void* d_out, int out_size) {
    const float* nbr       = (const float*)d_in[0];
    const float* angle_fea = (const float*)d_in[1];
    const int*   anb       = (const int*)d_in[2];
    const int*   ce        = (const int*)d_in[3];
    const int*   ca        = (const int*)d_in[4];
    const float* W_full    = (const float*)d_in[5];
    const float* W_mask    = (const float*)d_in[6];
    const float* gn1_g     = (const float*)d_in[7];
    const float* gn1_b     = (const float*)d_in[8];
    const float* gn2_g     = (const float*)d_in[9];
    const float* gn2_b     = (const float*)d_in[10];
    const float* W1a       = (const float*)d_in[11];
    const float* b1a       = (const float*)d_in[12];
    const float* W2a       = (const float*)d_in[13];
    const float* b2a       = (const float*)d_in[14];
    const float* W1b       = (const float*)d_in[15];
    const float* b1b       = (const float*)d_in[16];
    const float* W2b       = (const float*)d_in[17];
    const float* b2b       = (const float*)d_in[18];
    float* out = (float*)d_out;

    int n_edges  = in_sizes[0] / 64;
    int n_angles = in_sizes[1] / 40;

    k_zero<<<512, 256>>>(n_edges);
    dim3 g1(1024, 2);
    k_precompute<<<g1, 128>>>(nbr, W_full, n_edges);
    k_count<<<(n_angles + 255) / 256, 256>>>(anb, n_angles);
    k_scanA<<<SCAN_BLOCKS, 256>>>(n_edges);
    k_scanB<<<1, SCAN_BLOCKS>>>(n_edges);
    k_scanC<<<SCAN_BLOCKS, 256>>>(n_edges);
    k_fill<<<(n_angles + 255) / 256, 256>>>(anb, n_angles);
    int nblk = 4096;
    int chunk = ((n_angles + nblk - 1) / nblk + ATILE - 1) / ATILE * ATILE;
    k_angle_mma<<<nblk, 128>>>(angle_fea, anb, ca, W_full, n_angles, chunk);
    k_stats1<<<256, 128>>>(gn1_g, gn1_b);
    k_gather<<<2048, 256>>>(ca, ce, W_mask, n_edges);
    k_stats2<<<256, 64>>>(gn2_g, gn2_b);
    k_final<<<(n_edges + 255) / 256, 256>>>(nbr, ce, W1a, b1a, W2a, b2a,
                                            W1b, b1b, W2b, b2b, out, n_edges);
}

// round 11
// speedup vs baseline: 1.0648x; 1.0648x over previous
#include <cuda_runtime.h>
#include <cuda_fp16.h>
#include <math.h>

#define NE_MAX 200000
#define NA_MAX 1600000
#define ATILE 32
#define SCAN_BLOCKS 256

// ---- static scratch ----
__device__ __half g_P0h[(size_t)NE_MAX * 128];
__device__ __half g_P1h[(size_t)NE_MAX * 128];
__device__ __half g_gbufh[(size_t)NA_MAX * 128];
__device__ float g_csum[256 * 128];
__device__ float g_csumsq[256 * 128];
__device__ unsigned g_ccnt[256];
__device__ float g_a1[256 * 128];
__device__ float g_b1[256 * 128];
__device__ float g_summed[(size_t)NE_MAX * 64];
__device__ unsigned g_acnt[NE_MAX];
__device__ unsigned g_off[NE_MAX + 1];
__device__ unsigned g_curs[NE_MAX];
__device__ unsigned g_bucket[NA_MAX];   // aid | (crystal << 24)
__device__ unsigned g_blksum[SCAN_BLOCKS];
__device__ unsigned g_blkoff[SCAN_BLOCKS];
__device__ float g_esum[256 * 64];
__device__ float g_esumsq[256 * 64];
__device__ unsigned g_ecnt[256];
__device__ float g_a2[256 * 64];
__device__ float g_b2[256 * 64];

typedef unsigned long long ull;
__device__ __forceinline__ ull ffma2(ull a, ull b, ull c) {
    ull d; asm("fma.rn.f32x2 %0, %1, %2, %3;" : "=l"(d) : "l"(a), "l"(b), "l"(c)); return d;
}
__device__ __forceinline__ ull pack2(float x, float y) {
    ull d; asm("mov.b64 %0, {%1, %2};" : "=l"(d) : "f"(x), "f"(y)); return d;
}
__device__ __forceinline__ float2 unpack2(ull a) {
    float x, y; asm("mov.b64 {%0, %1}, %2;" : "=f"(x), "=f"(y) : "l"(a));
    return make_float2(x, y);
}
__device__ __forceinline__ float4 ld_half4(const __half* p) {
    uint2 u = *(const uint2*)p;
    float2 fa = __half22float2(*(__half2*)&u.x);
    float2 fb = __half22float2(*(__half2*)&u.y);
    return make_float4(fa.x, fa.y, fb.x, fb.y);
}
__device__ __forceinline__ void cp_async8(void* smem, const void* gmem) {
    unsigned s = (unsigned)__cvta_generic_to_shared(smem);
    asm volatile("cp.async.ca.shared.global [%0], [%1], 8;" :: "r"(s), "l"(gmem));
}
__device__ __forceinline__ void cp_async4(void* smem, const void* gmem) {
    unsigned s = (unsigned)__cvta_generic_to_shared(smem);
    asm volatile("cp.async.ca.shared.global [%0], [%1], 4;" :: "r"(s), "l"(gmem));
}
__device__ __forceinline__ void cp_commit() { asm volatile("cp.async.commit_group;" ::: "memory"); }
template <int N>
__device__ __forceinline__ void cp_wait() { asm volatile("cp.async.wait_group %0;" :: "n"(N) : "memory"); }
__device__ __forceinline__ void mma_16816(float c[4], unsigned a0, unsigned a1,
                                          unsigned a2, unsigned a3,
                                          unsigned b0, unsigned b1) {
    asm volatile(
        "mma.sync.aligned.m16n8k16.row.col.f32.f16.f16.f32 "
        "{%0,%1,%2,%3}, {%4,%5,%6,%7}, {%8,%9}, {%0,%1,%2,%3};"
        : "+f"(c[0]), "+f"(c[1]), "+f"(c[2]), "+f"(c[3])
        : "r"(a0), "r"(a1), "r"(a2), "r"(a3), "r"(b0), "r"(b1));
}

// ---- K0: zero accumulators ----
__global__ void k_zero(int n_edges) {
    int i = blockIdx.x * blockDim.x + threadIdx.x;
    int stride = gridDim.x * blockDim.x;
    for (int k = i; k < n_edges; k += stride) g_acnt[k] = 0u;
    for (int k = i; k < 256 * 128; k += stride) { g_csum[k] = 0.f; g_csumsq[k] = 0.f; }
    for (int k = i; k < 256 * 64; k += stride) { g_esum[k] = 0.f; g_esumsq[k] = 0.f; }
    for (int k = i; k < 256; k += stride) { g_ccnt[k] = 0u; g_ecnt[k] = 0u; }
}

// ---- K1: P0/P1 = nbr_fea @ W_full halves (fp16 out, k-packed FFMA2) ----
__global__ void __launch_bounds__(128) k_precompute(
        const float* __restrict__ nbr, const float* __restrict__ W_full, int n_edges) {
    int j = threadIdx.x;
    int half = blockIdx.y;
    ull w2[32];
    const float* wb = W_full + (size_t)(40 + half * 64) * 128 + j;
#pragma unroll
    for (int kk = 0; kk < 32; kk++)
        w2[kk] = pack2(wb[(size_t)(2 * kk) * 128], wb[(size_t)(2 * kk + 1) * 128]);
    __half* P = half ? g_P1h : g_P0h;
    __shared__ __align__(16) ull snb[2][32];
    int nb = gridDim.x;
    for (int e2 = blockIdx.x * 2; e2 < n_edges; e2 += nb * 2) {
        if (j < 64) {
            int g = j >> 5, jj = j & 31;
            int e = min(e2 + g, n_edges - 1);
            snb[g][jj] = ((const ull*)(nbr + (size_t)e * 64))[jj];
        }
        __syncthreads();
#pragma unroll 2
        for (int gg = 0; gg < 2; gg++) {
            int ee = e2 + gg;
            if (ee >= n_edges) break;
            ull acc = 0ull;
#pragma unroll
            for (int kk = 0; kk < 16; kk++) {
                ulonglong2 v = *(const ulonglong2*)&snb[gg][2 * kk];
                acc = ffma2(v.x, w2[2 * kk], acc);
                acc = ffma2(v.y, w2[2 * kk + 1], acc);
            }
            float2 u = unpack2(acc);
            P[(size_t)ee * 128 + j] = __float2half_rn(u.x + u.y);
        }
        __syncthreads();
    }
}

// ---- K2: count angles per src edge ----
__global__ void k_count(const int* __restrict__ anb, int n_angles) {
    int i = blockIdx.x * blockDim.x + threadIdx.x;
    if (i < n_angles) atomicAdd(&g_acnt[anb[2 * (size_t)i]], 1u);
}

// ---- K3: angle GEMM via HMMA tensor cores (R9 baseline) ----
__global__ void __launch_bounds__(128) k_angle_mma(
        const float* __restrict__ af, const int* __restrict__ anb,
        const float* __restrict__ W, int n_angles, int chunk) {
    int tid = threadIdx.x;
    int wid = tid >> 5, lane = tid & 31;
    int g = lane >> 2, t = lane & 3;
    int nbase = wid * 32;

    unsigned bfrag[4][3][2];
#pragma unroll
    for (int nt = 0; nt < 4; nt++)
#pragma unroll
        for (int ks = 0; ks < 3; ks++) {
            int ch = nbase + nt * 8 + g;
            int k0 = ks * 16 + 2 * t;
            float w00 = (k0 < 40)     ? __ldg(&W[(size_t)k0 * 128 + ch]) : 0.f;
            float w01 = (k0 + 1 < 40) ? __ldg(&W[(size_t)(k0 + 1) * 128 + ch]) : 0.f;
            float w10 = (k0 + 8 < 40) ? __ldg(&W[(size_t)(k0 + 8) * 128 + ch]) : 0.f;
            float w11 = (k0 + 9 < 40) ? __ldg(&W[(size_t)(k0 + 9) * 128 + ch]) : 0.f;
            __half2 h0 = __floats2half2_rn(w00, w01);
            __half2 h1 = __floats2half2_rn(w10, w11);
            bfrag[nt][ks][0] = *(unsigned*)&h0;
            bfrag[nt][ks][1] = *(unsigned*)&h1;
        }

    __shared__ __align__(16) ull s_af[2][ATILE * 20];
    __shared__ int s_ii[2][ATILE * 2];
    __shared__ __align__(16) __half sAh[32][56];

    for (int idx = tid; idx < 32 * 16; idx += 128)
        sAh[idx >> 4][40 + (idx & 15)] = __float2half(0.f);

    int a0 = blockIdx.x * chunk;
    int aend = min(a0 + chunk, n_angles);
    if (a0 >= aend) return;

    const ull* af2 = (const ull*)af;
    int maxf2 = n_angles * 20 - 1;
    int maxi  = n_angles - 1;

    {
#pragma unroll
        for (int r = 0; r < 5; r++) {
            int pos = r * 128 + tid;
            cp_async8(&s_af[0][pos], &af2[min(a0 * 20 + pos, maxf2)]);
        }
        if (tid < 64) cp_async4(&s_ii[0][tid], &anb[min(2 * a0 + tid, 2 * maxi + 1)]);
        cp_commit();
    }

    int buf = 0;
    for (int base = a0; base < aend; base += ATILE, buf ^= 1) {
        int nbase2 = base + ATILE;
        bool has_next = nbase2 < aend;
        if (has_next) {
#pragma unroll
            for (int r = 0; r < 5; r++) {
                int pos = r * 128 + tid;
                cp_async8(&s_af[buf ^ 1][pos], &af2[min(nbase2 * 20 + pos, maxf2)]);
            }
            if (tid < 64) cp_async4(&s_ii[buf ^ 1][tid], &anb[min(2 * nbase2 + tid, 2 * maxi + 1)]);
            cp_commit();
            cp_wait<1>();
        } else {
            cp_wait<0>();
        }
        __syncthreads();
        const float* afv = (const float*)s_af[buf];
#pragma unroll
        for (int q = 0; q < 10; q++) {
            int idx = q * 128 + tid;
            sAh[idx / 40][idx % 40] = __float2half_rn(afv[idx]);
        }
        __syncthreads();

#pragma unroll
        for (int mt = 0; mt < 2; mt++) {
            int rA = mt * 16 + g;
            int rB = rA + 8;
            int i0A = s_ii[buf][2 * rA], i1A = s_ii[buf][2 * rA + 1];
            int i0B = s_ii[buf][2 * rB], i1B = s_ii[buf][2 * rB + 1];
            unsigned p0A[4], p1A[4], p0B[4], p1B[4];
#pragma unroll
            for (int nt = 0; nt < 4; nt++) {
                int ch = nbase + nt * 8 + 2 * t;
                p0A[nt] = *(const unsigned*)&g_P0h[(size_t)i0A * 128 + ch];
                p1A[nt] = *(const unsigned*)&g_P1h[(size_t)i1A * 128 + ch];
                p0B[nt] = *(const unsigned*)&g_P0h[(size_t)i0B * 128 + ch];
                p1B[nt] = *(const unsigned*)&g_P1h[(size_t)i1B * 128 + ch];
            }
            float c[4][4];
#pragma unroll
            for (int nt = 0; nt < 4; nt++)
#pragma unroll
                for (int q = 0; q < 4; q++) c[nt][q] = 0.f;
#pragma unroll
            for (int ks = 0; ks < 3; ks++) {
                unsigned a0f = *(const unsigned*)&sAh[rA][ks * 16 + 2 * t];
                unsigned a1f = *(const unsigned*)&sAh[rB][ks * 16 + 2 * t];
                unsigned a2f = *(const unsigned*)&sAh[rA][ks * 16 + 2 * t + 8];
                unsigned a3f = *(const unsigned*)&sAh[rB][ks * 16 + 2 * t + 8];
#pragma unroll
                for (int nt = 0; nt < 4; nt++)
                    mma_16816(c[nt], a0f, a1f, a2f, a3f,
                              bfrag[nt][ks][0], bfrag[nt][ks][1]);
            }
            int angleA = base + rA;
            int angleB = base + rB;
#pragma unroll
            for (int nt = 0; nt < 4; nt++) {
                int ch = nbase + nt * 8 + 2 * t;
                if (angleA < aend) {
                    float2 q0 = __half22float2(*(__half2*)&p0A[nt]);
                    float2 q1 = __half22float2(*(__half2*)&p1A[nt]);
                    __half2 o = __floats2half2_rn(c[nt][0] + q0.x + q1.x,
                                                  c[nt][1] + q0.y + q1.y);
                    *(__half2*)&g_gbufh[(size_t)angleA * 128 + ch] = o;
                }
                if (angleB < aend) {
                    float2 q0 = __half22float2(*(__half2*)&p0B[nt]);
                    float2 q1 = __half22float2(*(__half2*)&p1B[nt]);
                    __half2 o = __floats2half2_rn(c[nt][2] + q0.x + q1.x,
                                                  c[nt][3] + q0.y + q1.y);
                    *(__half2*)&g_gbufh[(size_t)angleB * 128 + ch] = o;
                }
            }
        }
        __syncthreads();
    }
}

// ---- K3b: crystal stats over gbufh (sequential stream, 2-wide, sorted-ca flush) ----
__global__ void __launch_bounds__(256) k_stats_g(const int* __restrict__ ca, int n_angles) {
    int gw = blockIdx.x * (blockDim.x >> 5) + (threadIdx.x >> 5);
    int lane = threadIdx.x & 31;
    int totalw = gridDim.x * (blockDim.x >> 5);
    int chunk = (n_angles + totalw - 1) / totalw;
    int a0 = gw * chunk, aend = min(a0 + chunk, n_angles);
    if (a0 >= aend) return;
    float s0 = 0.f, s1 = 0.f, s2 = 0.f, s3 = 0.f;
    float q0 = 0.f, q1 = 0.f, q2 = 0.f, q3 = 0.f;
    int lcnt = 0;
    int curc = __ldg(&ca[a0]);
    int chb = 4 * lane;
    int a = a0;
    for (; a + 2 <= aend; a += 2) {
        int cA = __ldg(&ca[a]);
        int cB = __ldg(&ca[a + 1]);
        float4 xA = ld_half4(&g_gbufh[(size_t)a * 128 + chb]);
        float4 xB = ld_half4(&g_gbufh[(size_t)(a + 1) * 128 + chb]);
        if (cA != curc) {
            int b = curc * 128 + chb;
            atomicAdd(&g_csum[b + 0], s0); atomicAdd(&g_csum[b + 1], s1);
            atomicAdd(&g_csum[b + 2], s2); atomicAdd(&g_csum[b + 3], s3);
            atomicAdd(&g_csumsq[b + 0], q0); atomicAdd(&g_csumsq[b + 1], q1);
            atomicAdd(&g_csumsq[b + 2], q2); atomicAdd(&g_csumsq[b + 3], q3);
            if (lane == 0) atomicAdd(&g_ccnt[curc], (unsigned)lcnt);
            s0 = s1 = s2 = s3 = 0.f; q0 = q1 = q2 = q3 = 0.f;
            lcnt = 0; curc = cA;
        }
        s0 += xA.x; s1 += xA.y; s2 += xA.z; s3 += xA.w;
        q0 = fmaf(xA.x, xA.x, q0); q1 = fmaf(xA.y, xA.y, q1);
        q2 = fmaf(xA.z, xA.z, q2); q3 = fmaf(xA.w, xA.w, q3);
        lcnt++;
        if (cB != curc) {
            int b = curc * 128 + chb;
            atomicAdd(&g_csum[b + 0], s0); atomicAdd(&g_csum[b + 1], s1);
            atomicAdd(&g_csum[b + 2], s2); atomicAdd(&g_csum[b + 3], s3);
            atomicAdd(&g_csumsq[b + 0], q0); atomicAdd(&g_csumsq[b + 1], q1);
            atomicAdd(&g_csumsq[b + 2], q2); atomicAdd(&g_csumsq[b + 3], q3);
            if (lane == 0) atomicAdd(&g_ccnt[curc], (unsigned)lcnt);
            s0 = s1 = s2 = s3 = 0.f; q0 = q1 = q2 = q3 = 0.f;
            lcnt = 0; curc = cB;
        }
        s0 += xB.x; s1 += xB.y; s2 += xB.z; s3 += xB.w;
        q0 = fmaf(xB.x, xB.x, q0); q1 = fmaf(xB.y, xB.y, q1);
        q2 = fmaf(xB.z, xB.z, q2); q3 = fmaf(xB.w, xB.w, q3);
        lcnt++;
    }
    for (; a < aend; a++) {
        int c = __ldg(&ca[a]);
        float4 x = ld_half4(&g_gbufh[(size_t)a * 128 + chb]);
        if (c != curc) {
            int b = curc * 128 + chb;
            atomicAdd(&g_csum[b + 0], s0); atomicAdd(&g_csum[b + 1], s1);
            atomicAdd(&g_csum[b + 2], s2); atomicAdd(&g_csum[b + 3], s3);
            atomicAdd(&g_csumsq[b + 0], q0); atomicAdd(&g_csumsq[b + 1], q1);
            atomicAdd(&g_csumsq[b + 2], q2); atomicAdd(&g_csumsq[b + 3], q3);
            if (lane == 0) atomicAdd(&g_ccnt[curc], (unsigned)lcnt);
            s0 = s1 = s2 = s3 = 0.f; q0 = q1 = q2 = q3 = 0.f;
            lcnt = 0; curc = c;
        }
        s0 += x.x; s1 += x.y; s2 += x.z; s3 += x.w;
        q0 = fmaf(x.x, x.x, q0); q1 = fmaf(x.y, x.y, q1);
        q2 = fmaf(x.z, x.z, q2); q3 = fmaf(x.w, x.w, q3);
        lcnt++;
    }
    int b = curc * 128 + chb;
    atomicAdd(&g_csum[b + 0], s0); atomicAdd(&g_csum[b + 1], s1);
    atomicAdd(&g_csum[b + 2], s2); atomicAdd(&g_csum[b + 3], s3);
    atomicAdd(&g_csumsq[b + 0], q0); atomicAdd(&g_csumsq[b + 1], q1);
    atomicAdd(&g_csumsq[b + 2], q2); atomicAdd(&g_csumsq[b + 3], q3);
    if (lane == 0) atomicAdd(&g_ccnt[curc], (unsigned)lcnt);
}

// ---- K4: finalize crystal_norm1 affine ----
__global__ void k_stats1(const float* __restrict__ gn1_g, const float* __restrict__ gn1_b) {
    int c = blockIdx.x, j = threadIdx.x;
    float cnt = fmaxf((float)g_ccnt[c], 1.f);
    float mean = g_csum[c * 128 + j] / cnt;
    float var = fmaxf(g_csumsq[c * 128 + j] / cnt - mean * mean, 0.f);
    float inv = rsqrtf(var + 1e-5f);
    float a = gn1_g[j] * inv;
    g_a1[c * 128 + j] = a;
    g_b1[c * 128 + j] = gn1_b[j] - mean * a;
}

// ---- K5a/b/c: parallel exclusive scan over counts ----
__global__ void k_scanA(int n_edges) {
    __shared__ unsigned sred[256];
    int b = blockIdx.x, t = threadIdx.x;
    int per = (n_edges + SCAN_BLOCKS - 1) / SCAN_BLOCKS;
    int s = b * per, e = min(s + per, n_edges);
    unsigned local = 0;
    for (int i = s + t; i < e; i += 256) local += g_acnt[i];
    sred[t] = local;
    __syncthreads();
    for (int off = 128; off; off >>= 1) {
        if (t < off) sred[t] += sred[t + off];
        __syncthreads();
    }
    if (t == 0) g_blksum[b] = sred[0];
}
__global__ void k_scanB(int n_edges) {
    __shared__ unsigned ss[SCAN_BLOCKS];
    int t = threadIdx.x;
    ss[t] = g_blksum[t];
    __syncthreads();
    for (int off = 1; off < SCAN_BLOCKS; off <<= 1) {
        unsigned v = (t >= off) ? ss[t - off] : 0u;
        __syncthreads();
        if (t >= off) ss[t] += v;
        __syncthreads();
    }
    g_blkoff[t] = ss[t] - g_blksum[t];
    if (t == SCAN_BLOCKS - 1) g_off[n_edges] = ss[t];
}
__global__ void k_scanC(int n_edges) {
    __shared__ unsigned ss[256];
    int b = blockIdx.x, t = threadIdx.x;
    int per = (n_edges + SCAN_BLOCKS - 1) / SCAN_BLOCKS;
    int s0 = b * per, e0 = min(s0 + per, n_edges);
    int per2 = (per + 255) / 256;
    int s = s0 + t * per2, e = min(s + per2, e0);
    unsigned local = 0;
    for (int i = s; i < e; i++) local += g_acnt[i];
    ss[t] = local;
    __syncthreads();
    for (int off = 1; off < 256; off <<= 1) {
        unsigned v = (t >= off) ? ss[t - off] : 0u;
        __syncthreads();
        if (t >= off) ss[t] += v;
        __syncthreads();
    }
    unsigned run = g_blkoff[b] + ss[t] - local;
    for (int i = s; i < e; i++) {
        unsigned c = g_acnt[i];
        g_off[i] = run;
        g_curs[i] = run;
        run += c;
    }
}

// ---- K6: fill CSR buckets, crystal id packed into high bits ----
__global__ void k_fill(const int* __restrict__ anb, const int* __restrict__ ca,
                       int n_angles) {
    int i = blockIdx.x * blockDim.x + threadIdx.x;
    if (i < n_angles) {
        int s = anb[2 * (size_t)i];
        unsigned p = atomicAdd(&g_curs[s], 1u);
        g_bucket[p] = (unsigned)i | ((unsigned)ca[i] << 24);
    }
}

// ---- K7: fused gate+gather, packed-bucket (2 dependent loads, not 3) ----
__global__ void __launch_bounds__(256) k_gather(const int* __restrict__ ce,
                                                const float* __restrict__ W_mask,
                                                int n_edges) {
    int gw = blockIdx.x * (blockDim.x >> 5) + (threadIdx.x >> 5);
    int lane = threadIdx.x & 31;
    int totalw = gridDim.x * (blockDim.x >> 5);
    int chunk = (n_edges + totalw - 1) / totalw;
    int e0 = gw * chunk, eend = min(e0 + chunk, n_edges);
    if (e0 >= eend) return;
    float4 wm = make_float4(0.f, 0.f, 0.f, 0.f);
    if (lane >= 16) wm = ((const float4*)W_mask)[lane - 16];
    float4 lsum = make_float4(0.f, 0.f, 0.f, 0.f);
    float4 lsq  = make_float4(0.f, 0.f, 0.f, 0.f);
    int lcnt = 0;
    int curc = __ldg(&ce[e0]);
    for (int e = e0; e < eend; e++) {
        int c = __ldg(&ce[e]);
        if (c != curc) {
            if (lane < 16) {
                int b = curc * 64 + 4 * lane;
                atomicAdd(&g_esum[b + 0], lsum.x); atomicAdd(&g_esum[b + 1], lsum.y);
                atomicAdd(&g_esum[b + 2], lsum.z); atomicAdd(&g_esum[b + 3], lsum.w);
                atomicAdd(&g_esumsq[b + 0], lsq.x); atomicAdd(&g_esumsq[b + 1], lsq.y);
                atomicAdd(&g_esumsq[b + 2], lsq.z); atomicAdd(&g_esumsq[b + 3], lsq.w);
            }
            if (lane == 0) atomicAdd(&g_ecnt[curc], (unsigned)lcnt);
            lsum = make_float4(0.f, 0.f, 0.f, 0.f);
            lsq = make_float4(0.f, 0.f, 0.f, 0.f);
            lcnt = 0; curc = c;
        }
        unsigned s = g_off[e], t = g_off[e + 1];
        float4 acc = make_float4(0.f, 0.f, 0.f, 0.f);
        for (unsigned p = s; p < t; p += 2) {
            bool two = (p + 1 < t);
            unsigned vA = __ldg(&g_bucket[p]);
            unsigned vB = two ? __ldg(&g_bucket[p + 1]) : vA;
            int aidA = vA & 0xFFFFFFu, ccA = vA >> 24;
            int aidB = vB & 0xFFFFFFu, ccB = vB >> 24;
            float4 gA = ld_half4(&g_gbufh[(size_t)aidA * 128 + 4 * lane]);
            float4 gB = ld_half4(&g_gbufh[(size_t)aidB * 128 + 4 * lane]);
            float4 aA = *(const float4*)&g_a1[ccA * 128 + 4 * lane];
            float4 bA = *(const float4*)&g_b1[ccA * 128 + 4 * lane];
            float4 aB = *(const float4*)&g_a1[ccB * 128 + 4 * lane];
            float4 bB = *(const float4*)&g_b1[ccB * 128 + 4 * lane];
            float xA0 = fmaf(gA.x, aA.x, bA.x), xA1 = fmaf(gA.y, aA.y, bA.y);
            float xA2 = fmaf(gA.z, aA.z, bA.z), xA3 = fmaf(gA.w, aA.w, bA.w);
            float xB0 = fmaf(gB.x, aB.x, bB.x), xB1 = fmaf(gB.y, aB.y, bB.y);
            float xB2 = fmaf(gB.z, aB.z, bB.z), xB3 = fmaf(gB.w, aB.w, bB.w);
            float pA = xA0 * wm.x + xA1 * wm.y + xA2 * wm.z + xA3 * wm.w;
            float pB = xB0 * wm.x + xB1 * wm.y + xB2 * wm.z + xB3 * wm.w;
#pragma unroll
            for (int o = 16; o; o >>= 1) {
                pA += __shfl_xor_sync(0xffffffffu, pA, o);
                pB += __shfl_xor_sync(0xffffffffu, pB, o);
            }
            float fA = 1.f - 2.f / (__expf(2.f * pA) + 1.f);
            float fB = 1.f - 2.f / (__expf(2.f * pB) + 1.f);
            acc.x += fA * fmaxf(xA0, 0.f);
            acc.y += fA * fmaxf(xA1, 0.f);
            acc.z += fA * fmaxf(xA2, 0.f);
            acc.w += fA * fmaxf(xA3, 0.f);
            if (two) {
                acc.x += fB * fmaxf(xB0, 0.f);
                acc.y += fB * fmaxf(xB1, 0.f);
                acc.z += fB * fmaxf(xB2, 0.f);
                acc.w += fB * fmaxf(xB3, 0.f);
            }
        }
        float inv = 1.f / fmaxf((float)(t - s), 1.f);
        float4 v = make_float4(acc.x * inv, acc.y * inv, acc.z * inv, acc.w * inv);
        if (lane < 16) {
            *(float4*)&g_summed[(size_t)e * 64 + 4 * lane] = v;
            lsum.x += v.x; lsum.y += v.y; lsum.z += v.z; lsum.w += v.w;
            lsq.x += v.x * v.x; lsq.y += v.y * v.y; lsq.z += v.z * v.z; lsq.w += v.w * v.w;
        }
        lcnt++;
    }
    if (lane < 16) {
        int b = curc * 64 + 4 * lane;
        atomicAdd(&g_esum[b + 0], lsum.x); atomicAdd(&g_esum[b + 1], lsum.y);
        atomicAdd(&g_esum[b + 2], lsum.z); atomicAdd(&g_esum[b + 3], lsum.w);
        atomicAdd(&g_esumsq[b + 0], lsq.x); atomicAdd(&g_esumsq[b + 1], lsq.y);
        atomicAdd(&g_esumsq[b + 2], lsq.z); atomicAdd(&g_esumsq[b + 3], lsq.w);
    }
    if (lane == 0) atomicAdd(&g_ecnt[curc], (unsigned)lcnt);
}

// ---- K9: finalize crystal_norm2 affine ----
__global__ void k_stats2(const float* __restrict__ gn2_g, const float* __restrict__ gn2_b) {
    int c = blockIdx.x, j = threadIdx.x;
    float cnt = fmaxf((float)g_ecnt[c], 1.f);
    float mean = g_esum[c * 64 + j] / cnt;
    float var = fmaxf(g_esumsq[c * 64 + j] / cnt - mean * mean, 0.f);
    float inv = rsqrtf(var + 1e-5f);
    float a = gn2_g[j] * inv;
    g_a2[c * 64 + j] = a;
    g_b2[c * 64 + j] = gn2_b[j] - mean * a;
}

// ---- K10: thread-per-edge residual MLPs ----
__global__ void __launch_bounds__(256) k_final(
        const float* __restrict__ nbr, const int* __restrict__ ce,
        const float* __restrict__ W1a, const float* __restrict__ b1a,
        const float* __restrict__ W2a, const float* __restrict__ b2a,
        const float* __restrict__ W1b, const float* __restrict__ b1b,
        const float* __restrict__ W2b, const float* __restrict__ b2b,
        float* __restrict__ out, int n_edges) {
    __shared__ float4 sW1a[512], sW2a[512], sW1b[512], sW2b[512];
    __shared__ float sb1a[32], sb2a[64], sb1b[32], sb2b[64];
    int t = threadIdx.x;
    for (int k = t; k < 512; k += 256) {
        sW1a[k] = ((const float4*)W1a)[k];
        sW2a[k] = ((const float4*)W2a)[k];
        sW1b[k] = ((const float4*)W1b)[k];
        sW2b[k] = ((const float4*)W2b)[k];
    }
    if (t < 32) { sb1a[t] = b1a[t]; sb1b[t] = b1b[t]; }
    if (t < 64) { sb2a[t] = b2a[t]; sb2b[t] = b2b[t]; }
    __syncthreads();
    int e = blockIdx.x * 256 + t;
    if (e >= n_edges) return;

    float h[64];
    int c = __ldg(&ce[e]);
    {
        const float4* s4 = (const float4*)&g_summed[(size_t)e * 64];
        const float4* a4 = (const float4*)&g_a2[c * 64];
        const float4* b4 = (const float4*)&g_b2[c * 64];
#pragma unroll
        for (int i = 0; i < 16; i++) {
            float4 sv = s4[i], av = a4[i], bv = b4[i];
            h[4 * i + 0] = fmaf(sv.x, av.x, bv.x);
            h[4 * i + 1] = fmaf(sv.y, av.y, bv.y);
            h[4 * i + 2] = fmaf(sv.z, av.z, bv.z);
            h[4 * i + 3] = fmaf(sv.w, av.w, bv.w);
        }
    }
    float r[32];
    {
        ull racc[16];
#pragma unroll
        for (int j = 0; j < 16; j++) racc[j] = pack2(sb1a[2 * j], sb1a[2 * j + 1]);
#pragma unroll
        for (int k = 0; k < 64; k++) {
            ull hk = pack2(h[k], h[k]);
#pragma unroll
            for (int j = 0; j < 8; j++) {
                float4 w4 = sW1a[k * 8 + j];
                racc[2 * j]     = ffma2(hk, pack2(w4.x, w4.y), racc[2 * j]);
                racc[2 * j + 1] = ffma2(hk, pack2(w4.z, w4.w), racc[2 * j + 1]);
            }
        }
#pragma unroll
        for (int j = 0; j < 16; j++) {
            float2 u = unpack2(racc[j]);
            r[2 * j] = fmaxf(u.x, 0.f);
            r[2 * j + 1] = fmaxf(u.y, 0.f);
        }
        ull hacc[32];
#pragma unroll
        for (int j = 0; j < 32; j++) hacc[j] = pack2(h[2 * j] + sb2a[2 * j], h[2 * j + 1] + sb2a[2 * j + 1]);
#pragma unroll
        for (int k = 0; k < 32; k++) {
            ull rk = pack2(r[k], r[k]);
#pragma unroll
            for (int j = 0; j < 16; j++) {
                float4 w4 = sW2a[k * 16 + j];
                hacc[2 * j]     = ffma2(rk, pack2(w4.x, w4.y), hacc[2 * j]);
                hacc[2 * j + 1] = ffma2(rk, pack2(w4.z, w4.w), hacc[2 * j + 1]);
            }
        }
#pragma unroll
        for (int j = 0; j < 32; j++) {
            float2 u = unpack2(hacc[j]);
            h[2 * j] = u.x; h[2 * j + 1] = u.y;
        }
    }
    {
        ull racc[16];
#pragma unroll
        for (int j = 0; j < 16; j++) racc[j] = pack2(sb1b[2 * j], sb1b[2 * j + 1]);
#pragma unroll
        for (int k = 0; k < 64; k++) {
            ull hk = pack2(h[k], h[k]);
#pragma unroll
            for (int j = 0; j < 8; j++) {
                float4 w4 = sW1b[k * 8 + j];
                racc[2 * j]     = ffma2(hk, pack2(w4.x, w4.y), racc[2 * j]);
                racc[2 * j + 1] = ffma2(hk, pack2(w4.z, w4.w), racc[2 * j + 1]);
            }
        }
#pragma unroll
        for (int j = 0; j < 16; j++) {
            float2 u = unpack2(racc[j]);
            r[2 * j] = fmaxf(u.x, 0.f);
            r[2 * j + 1] = fmaxf(u.y, 0.f);
        }
        ull hacc[32];
#pragma unroll
        for (int j = 0; j < 32; j++) hacc[j] = pack2(h[2 * j] + sb2b[2 * j], h[2 * j + 1] + sb2b[2 * j + 1]);
#pragma unroll
        for (int k = 0; k < 32; k++) {
            ull rk = pack2(r[k], r[k]);
#pragma unroll
            for (int j = 0; j < 16; j++) {
                float4 w4 = sW2b[k * 16 + j];
                hacc[2 * j]     = ffma2(rk, pack2(w4.x, w4.y), hacc[2 * j]);
                hacc[2 * j + 1] = ffma2(rk, pack2(w4.z, w4.w), hacc[2 * j + 1]);
            }
        }
#pragma unroll
        for (int j = 0; j < 32; j++) {
            float2 u = unpack2(hacc[j]);
            h[2 * j] = u.x; h[2 * j + 1] = u.y;
        }
    }
    {
        const float4* n4 = (const float4*)&nbr[(size_t)e * 64];
        float4* o4 = (float4*)&out[(size_t)e * 64];
#pragma unroll
        for (int i = 0; i < 16; i++) {
            float4 nv = n4[i];
            float4 ov;
            ov.x = 0.7071067811865476f * fmaxf(nv.x + h[4 * i + 0], 0.f);
            ov.y = 0.7071067811865476f * fmaxf(nv.y + h[4 * i + 1], 0.f);
            ov.z = 0.7071067811865476f * fmaxf(nv.z + h[4 * i + 2], 0.f);
            ov.w = 0.7071067811865476f * fmaxf(nv.w + h[4 * i + 3], 0.f);
            o4[i] = ov;
        }
    }
}

extern "C" void kernel_launch(void* const* d_in, const int* in_sizes, int n_in,
                              void* d_out, int out_size) {
    const float* nbr       = (const float*)d_in[0];
    const float* angle_fea = (const float*)d_in[1];
    const int*   anb       = (const int*)d_in[2];
    const int*   ce        = (const int*)d_in[3];
    const int*   ca        = (const int*)d_in[4];
    const float* W_full    = (const float*)d_in[5];
    const float* W_mask    = (const float*)d_in[6];
    const float* gn1_g     = (const float*)d_in[7];
    const float* gn1_b     = (const float*)d_in[8];
    const float* gn2_g     = (const float*)d_in[9];
    const float* gn2_b     = (const float*)d_in[10];
    const float* W1a       = (const float*)d_in[11];
    const float* b1a       = (const float*)d_in[12];
    const float* W2a       = (const float*)d_in[13];
    const float* b2a       = (const float*)d_in[14];
    const float* W1b       = (const float*)d_in[15];
    const float* b1b       = (const float*)d_in[16];
    const float* W2b       = (const float*)d_in[17];
    const float* b2b       = (const float*)d_in[18];
    float* out = (float*)d_out;

    int n_edges  = in_sizes[0] / 64;
    int n_angles = in_sizes[1] / 40;

    k_zero<<<512, 256>>>(n_edges);
    dim3 g1(1024, 2);
    k_precompute<<<g1, 128>>>(nbr, W_full, n_edges);
    k_count<<<(n_angles + 255) / 256, 256>>>(anb, n_angles);
    k_scanA<<<SCAN_BLOCKS, 256>>>(n_edges);
    k_scanB<<<1, SCAN_BLOCKS>>>(n_edges);
    k_scanC<<<SCAN_BLOCKS, 256>>>(n_edges);
    k_fill<<<(n_angles + 255) / 256, 256>>>(anb, ca, n_angles);
    int nblk = 4096;
    int chunk = ((n_angles + nblk - 1) / nblk + ATILE - 1) / ATILE * ATILE;
    k_angle_mma<<<nblk, 128>>>(angle_fea, anb, W_full, n_angles, chunk);
    k_stats_g<<<2048, 256>>>(ca, n_angles);
    k_stats1<<<256, 128>>>(gn1_g, gn1_b);
    k_gather<<<2048, 256>>>(ce, W_mask, n_edges);
    k_stats2<<<256, 64>>>(gn2_g, gn2_b);
    k_final<<<(n_edges + 255) / 256, 256>>>(nbr, ce, W1a, b1a, W2a, b2a,
                                            W1b, b1b, W2b, b2b, out, n_edges);
}

// round 12
// speedup vs baseline: 1.1869x; 1.1148x over previous
#include <cuda_runtime.h>
#include <cuda_fp16.h>
#include <math.h>

#define NE_MAX 200000
#define NA_MAX 1600000
#define ATILE 32
#define SCAN_BLOCKS 256
#define SP_STRIDE 136   // halfs; gives bank = 4g+t (conflict-free)

// ---- static scratch ----
__device__ __half g_P0h[(size_t)NE_MAX * 128];
__device__ __half g_P1h[(size_t)NE_MAX * 128];
__device__ __half g_gbufh[(size_t)NA_MAX * 128];
__device__ float g_csum[256 * 128];
__device__ float g_csumsq[256 * 128];
__device__ unsigned g_ccnt[256];
__device__ float g_a1[256 * 128];
__device__ float g_b1[256 * 128];
__device__ float g_summed[(size_t)NE_MAX * 64];
__device__ unsigned g_acnt[NE_MAX];
__device__ unsigned g_off[NE_MAX + 1];
__device__ unsigned g_curs[NE_MAX];
__device__ unsigned g_bucket[NA_MAX];   // aid | (crystal << 24)
__device__ unsigned g_blksum[SCAN_BLOCKS];
__device__ unsigned g_blkoff[SCAN_BLOCKS];
__device__ float g_esum[256 * 64];
__device__ float g_esumsq[256 * 64];
__device__ unsigned g_ecnt[256];
__device__ float g_a2[256 * 64];
__device__ float g_b2[256 * 64];

typedef unsigned long long ull;
__device__ __forceinline__ ull ffma2(ull a, ull b, ull c) {
    ull d; asm("fma.rn.f32x2 %0, %1, %2, %3;" : "=l"(d) : "l"(a), "l"(b), "l"(c)); return d;
}
__device__ __forceinline__ ull pack2(float x, float y) {
    ull d; asm("mov.b64 %0, {%1, %2};" : "=l"(d) : "f"(x), "f"(y)); return d;
}
__device__ __forceinline__ float2 unpack2(ull a) {
    float x, y; asm("mov.b64 {%0, %1}, %2;" : "=f"(x), "=f"(y) : "l"(a));
    return make_float2(x, y);
}
__device__ __forceinline__ float4 ld_half4(const __half* p) {
    uint2 u = *(const uint2*)p;
    float2 fa = __half22float2(*(__half2*)&u.x);
    float2 fb = __half22float2(*(__half2*)&u.y);
    return make_float4(fa.x, fa.y, fb.x, fb.y);
}
__device__ __forceinline__ void cp_async8(void* smem, const void* gmem) {
    unsigned s = (unsigned)__cvta_generic_to_shared(smem);
    asm volatile("cp.async.ca.shared.global [%0], [%1], 8;" :: "r"(s), "l"(gmem));
}
__device__ __forceinline__ void cp_async16(void* smem, const void* gmem) {
    unsigned s = (unsigned)__cvta_generic_to_shared(smem);
    asm volatile("cp.async.cg.shared.global [%0], [%1], 16;" :: "r"(s), "l"(gmem));
}
__device__ __forceinline__ void cp_async4(void* smem, const void* gmem) {
    unsigned s = (unsigned)__cvta_generic_to_shared(smem);
    asm volatile("cp.async.ca.shared.global [%0], [%1], 4;" :: "r"(s), "l"(gmem));
}
__device__ __forceinline__ void cp_commit() { asm volatile("cp.async.commit_group;" ::: "memory"); }
template <int N>
__device__ __forceinline__ void cp_wait() { asm volatile("cp.async.wait_group %0;" :: "n"(N) : "memory"); }
__device__ __forceinline__ void mma_16816(float c[4], unsigned a0, unsigned a1,
                                          unsigned a2, unsigned a3,
                                          unsigned b0, unsigned b1) {
    asm volatile(
        "mma.sync.aligned.m16n8k16.row.col.f32.f16.f16.f32 "
        "{%0,%1,%2,%3}, {%4,%5,%6,%7}, {%8,%9}, {%0,%1,%2,%3};"
        : "+f"(c[0]), "+f"(c[1]), "+f"(c[2]), "+f"(c[3])
        : "r"(a0), "r"(a1), "r"(a2), "r"(a3), "r"(b0), "r"(b1));
}

// ---- K0: zero accumulators ----
__global__ void k_zero(int n_edges) {
    int i = blockIdx.x * blockDim.x + threadIdx.x;
    int stride = gridDim.x * blockDim.x;
    for (int k = i; k < n_edges; k += stride) g_acnt[k] = 0u;
    for (int k = i; k < 256 * 128; k += stride) { g_csum[k] = 0.f; g_csumsq[k] = 0.f; }
    for (int k = i; k < 256 * 64; k += stride) { g_esum[k] = 0.f; g_esumsq[k] = 0.f; }
    for (int k = i; k < 256; k += stride) { g_ccnt[k] = 0u; g_ecnt[k] = 0u; }
}

// ---- K1: P0/P1 = nbr_fea @ W_full halves (fp16 out, k-packed FFMA2) ----
__global__ void __launch_bounds__(128) k_precompute(
        const float* __restrict__ nbr, const float* __restrict__ W_full, int n_edges) {
    int j = threadIdx.x;
    int half = blockIdx.y;
    ull w2[32];
    const float* wb = W_full + (size_t)(40 + half * 64) * 128 + j;
#pragma unroll
    for (int kk = 0; kk < 32; kk++)
        w2[kk] = pack2(wb[(size_t)(2 * kk) * 128], wb[(size_t)(2 * kk + 1) * 128]);
    __half* P = half ? g_P1h : g_P0h;
    __shared__ __align__(16) ull snb[2][32];
    int nb = gridDim.x;
    for (int e2 = blockIdx.x * 2; e2 < n_edges; e2 += nb * 2) {
        if (j < 64) {
            int g = j >> 5, jj = j & 31;
            int e = min(e2 + g, n_edges - 1);
            snb[g][jj] = ((const ull*)(nbr + (size_t)e * 64))[jj];
        }
        __syncthreads();
#pragma unroll 2
        for (int gg = 0; gg < 2; gg++) {
            int ee = e2 + gg;
            if (ee >= n_edges) break;
            ull acc = 0ull;
#pragma unroll
            for (int kk = 0; kk < 16; kk++) {
                ulonglong2 v = *(const ulonglong2*)&snb[gg][2 * kk];
                acc = ffma2(v.x, w2[2 * kk], acc);
                acc = ffma2(v.y, w2[2 * kk + 1], acc);
            }
            float2 u = unpack2(acc);
            P[(size_t)ee * 128 + j] = __float2half_rn(u.x + u.y);
        }
        __syncthreads();
    }
}

// ---- K2: count angles per src edge ----
__global__ void k_count(const int* __restrict__ anb, int n_angles) {
    int i = blockIdx.x * blockDim.x + threadIdx.x;
    if (i < n_angles) atomicAdd(&g_acnt[anb[2 * (size_t)i]], 1u);
}

// ---- K3: angle GEMM via HMMA; P rows staged in smem via coalesced cp.async ----
__global__ void __launch_bounds__(128) k_angle_mma(
        const float* __restrict__ af, const int* __restrict__ anb,
        const float* __restrict__ W, int n_angles, int chunk) {
    int tid = threadIdx.x;
    int wid = tid >> 5, lane = tid & 31;
    int g = lane >> 2, t = lane & 3;
    int nbase = wid * 32;

    unsigned bfrag[4][3][2];
#pragma unroll
    for (int nt = 0; nt < 4; nt++)
#pragma unroll
        for (int ks = 0; ks < 3; ks++) {
            int ch = nbase + nt * 8 + g;
            int k0 = ks * 16 + 2 * t;
            float w00 = (k0 < 40)     ? __ldg(&W[(size_t)k0 * 128 + ch]) : 0.f;
            float w01 = (k0 + 1 < 40) ? __ldg(&W[(size_t)(k0 + 1) * 128 + ch]) : 0.f;
            float w10 = (k0 + 8 < 40) ? __ldg(&W[(size_t)(k0 + 8) * 128 + ch]) : 0.f;
            float w11 = (k0 + 9 < 40) ? __ldg(&W[(size_t)(k0 + 9) * 128 + ch]) : 0.f;
            __half2 h0 = __floats2half2_rn(w00, w01);
            __half2 h1 = __floats2half2_rn(w10, w11);
            bfrag[nt][ks][0] = *(unsigned*)&h0;
            bfrag[nt][ks][1] = *(unsigned*)&h1;
        }

    __shared__ __align__(16) ull s_af[2][ATILE * 20];
    __shared__ int s_ii[2][ATILE * 2];
    __shared__ __align__(16) __half sAh[32][56];
    __shared__ __align__(16) __half sP[64][SP_STRIDE];  // rows 0..31: P0, 32..63: P1

    for (int idx = tid; idx < 32 * 16; idx += 128)
        sAh[idx >> 4][40 + (idx & 15)] = __float2half(0.f);

    int a0 = blockIdx.x * chunk;
    int aend = min(a0 + chunk, n_angles);
    if (a0 >= aend) return;

    const ull* af2 = (const ull*)af;
    int maxf2 = n_angles * 20 - 1;
    int maxi  = n_angles - 1;

    {
#pragma unroll
        for (int r = 0; r < 5; r++) {
            int pos = r * 128 + tid;
            cp_async8(&s_af[0][pos], &af2[min(a0 * 20 + pos, maxf2)]);
        }
        if (tid < 64) cp_async4(&s_ii[0][tid], &anb[min(2 * a0 + tid, 2 * maxi + 1)]);
        cp_commit();
    }

    int buf = 0;
    for (int base = a0; base < aend; base += ATILE, buf ^= 1) {
        int nbase2 = base + ATILE;
        bool has_next = nbase2 < aend;
        cp_wait<0>();          // current tile's af/ii ready
        __syncthreads();

        // ---- group P: stage 64 P-rows into sP, coalesced 16B chunks ----
#pragma unroll
        for (int q = 0; q < 8; q++) {
            int cidx = q * 128 + tid;      // 0..1023
            int row = cidx >> 4;           // 0..63
            int off = (cidx & 15) * 8;     // half offset within row
            int idx = (row < 32) ? s_ii[buf][2 * row] : s_ii[buf][2 * (row - 32) + 1];
            const __half* src = (row < 32) ? &g_P0h[(size_t)idx * 128 + off]
                                           : &g_P1h[(size_t)idx * 128 + off];
            cp_async16(&sP[row][off], src);
        }
        cp_commit();

        // ---- group af-next ----
        if (has_next) {
#pragma unroll
            for (int r = 0; r < 5; r++) {
                int pos = r * 128 + tid;
                cp_async8(&s_af[buf ^ 1][pos], &af2[min(nbase2 * 20 + pos, maxf2)]);
            }
            if (tid < 64) cp_async4(&s_ii[buf ^ 1][tid], &anb[min(2 * nbase2 + tid, 2 * maxi + 1)]);
            cp_commit();
        }

        // convert af -> fp16 (overlaps P loads)
        const float* afv = (const float*)s_af[buf];
#pragma unroll
        for (int q = 0; q < 10; q++) {
            int idx = q * 128 + tid;
            sAh[idx / 40][idx % 40] = __float2half_rn(afv[idx]);
        }
        if (has_next) cp_wait<1>(); else cp_wait<0>();   // P group done
        __syncthreads();

#pragma unroll
        for (int mt = 0; mt < 2; mt++) {
            int rA = mt * 16 + g;
            int rB = rA + 8;
            float c[4][4];
#pragma unroll
            for (int nt = 0; nt < 4; nt++)
#pragma unroll
                for (int q = 0; q < 4; q++) c[nt][q] = 0.f;
#pragma unroll
            for (int ks = 0; ks < 3; ks++) {
                unsigned a0f = *(const unsigned*)&sAh[rA][ks * 16 + 2 * t];
                unsigned a1f = *(const unsigned*)&sAh[rB][ks * 16 + 2 * t];
                unsigned a2f = *(const unsigned*)&sAh[rA][ks * 16 + 2 * t + 8];
                unsigned a3f = *(const unsigned*)&sAh[rB][ks * 16 + 2 * t + 8];
#pragma unroll
                for (int nt = 0; nt < 4; nt++)
                    mma_16816(c[nt], a0f, a1f, a2f, a3f,
                              bfrag[nt][ks][0], bfrag[nt][ks][1]);
            }
            int angleA = base + rA;
            int angleB = base + rB;
#pragma unroll
            for (int nt = 0; nt < 4; nt++) {
                int ch = nbase + nt * 8 + 2 * t;
                if (angleA < aend) {
                    float2 q0 = __half22float2(*(const __half2*)&sP[rA][ch]);
                    float2 q1 = __half22float2(*(const __half2*)&sP[32 + rA][ch]);
                    __half2 o = __floats2half2_rn(c[nt][0] + q0.x + q1.x,
                                                  c[nt][1] + q0.y + q1.y);
                    *(__half2*)&g_gbufh[(size_t)angleA * 128 + ch] = o;
                }
                if (angleB < aend) {
                    float2 q0 = __half22float2(*(const __half2*)&sP[rB][ch]);
                    float2 q1 = __half22float2(*(const __half2*)&sP[32 + rB][ch]);
                    __half2 o = __floats2half2_rn(c[nt][2] + q0.x + q1.x,
                                                  c[nt][3] + q0.y + q1.y);
                    *(__half2*)&g_gbufh[(size_t)angleB * 128 + ch] = o;
                }
            }
        }
        __syncthreads();
    }
}

// ---- K3b: crystal stats over gbufh (sequential stream, 2-wide, sorted-ca flush) ----
__global__ void __launch_bounds__(256) k_stats_g(const int* __restrict__ ca, int n_angles) {
    int gw = blockIdx.x * (blockDim.x >> 5) + (threadIdx.x >> 5);
    int lane = threadIdx.x & 31;
    int totalw = gridDim.x * (blockDim.x >> 5);
    int chunk = (n_angles + totalw - 1) / totalw;
    int a0 = gw * chunk, aend = min(a0 + chunk, n_angles);
    if (a0 >= aend) return;
    float s0 = 0.f, s1 = 0.f, s2 = 0.f, s3 = 0.f;
    float q0 = 0.f, q1 = 0.f, q2 = 0.f, q3 = 0.f;
    int lcnt = 0;
    int curc = __ldg(&ca[a0]);
    int chb = 4 * lane;
    int a = a0;
    for (; a + 2 <= aend; a += 2) {
        int cA = __ldg(&ca[a]);
        int cB = __ldg(&ca[a + 1]);
        float4 xA = ld_half4(&g_gbufh[(size_t)a * 128 + chb]);
        float4 xB = ld_half4(&g_gbufh[(size_t)(a + 1) * 128 + chb]);
        if (cA != curc) {
            int b = curc * 128 + chb;
            atomicAdd(&g_csum[b + 0], s0); atomicAdd(&g_csum[b + 1], s1);
            atomicAdd(&g_csum[b + 2], s2); atomicAdd(&g_csum[b + 3], s3);
            atomicAdd(&g_csumsq[b + 0], q0); atomicAdd(&g_csumsq[b + 1], q1);
            atomicAdd(&g_csumsq[b + 2], q2); atomicAdd(&g_csumsq[b + 3], q3);
            if (lane == 0) atomicAdd(&g_ccnt[curc], (unsigned)lcnt);
            s0 = s1 = s2 = s3 = 0.f; q0 = q1 = q2 = q3 = 0.f;
            lcnt = 0; curc = cA;
        }
        s0 += xA.x; s1 += xA.y; s2 += xA.z; s3 += xA.w;
        q0 = fmaf(xA.x, xA.x, q0); q1 = fmaf(xA.y, xA.y, q1);
        q2 = fmaf(xA.z, xA.z, q2); q3 = fmaf(xA.w, xA.w, q3);
        lcnt++;
        if (cB != curc) {
            int b = curc * 128 + chb;
            atomicAdd(&g_csum[b + 0], s0); atomicAdd(&g_csum[b + 1], s1);
            atomicAdd(&g_csum[b + 2], s2); atomicAdd(&g_csum[b + 3], s3);
            atomicAdd(&g_csumsq[b + 0], q0); atomicAdd(&g_csumsq[b + 1], q1);
            atomicAdd(&g_csumsq[b + 2], q2); atomicAdd(&g_csumsq[b + 3], q3);
            if (lane == 0) atomicAdd(&g_ccnt[curc], (unsigned)lcnt);
            s0 = s1 = s2 = s3 = 0.f; q0 = q1 = q2 = q3 = 0.f;
            lcnt = 0; curc = cB;
        }
        s0 += xB.x; s1 += xB.y; s2 += xB.z; s3 += xB.w;
        q0 = fmaf(xB.x, xB.x, q0); q1 = fmaf(xB.y, xB.y, q1);
        q2 = fmaf(xB.z, xB.z, q2); q3 = fmaf(xB.w, xB.w, q3);
        lcnt++;
    }
    for (; a < aend; a++) {
        int c = __ldg(&ca[a]);
        float4 x = ld_half4(&g_gbufh[(size_t)a * 128 + chb]);
        if (c != curc) {
            int b = curc * 128 + chb;
            atomicAdd(&g_csum[b + 0], s0); atomicAdd(&g_csum[b + 1], s1);
            atomicAdd(&g_csum[b + 2], s2); atomicAdd(&g_csum[b + 3], s3);
            atomicAdd(&g_csumsq[b + 0], q0); atomicAdd(&g_csumsq[b + 1], q1);
            atomicAdd(&g_csumsq[b + 2], q2); atomicAdd(&g_csumsq[b + 3], q3);
            if (lane == 0) atomicAdd(&g_ccnt[curc], (unsigned)lcnt);
            s0 = s1 = s2 = s3 = 0.f; q0 = q1 = q2 = q3 = 0.f;
            lcnt = 0; curc = c;
        }
        s0 += x.x; s1 += x.y; s2 += x.z; s3 += x.w;
        q0 = fmaf(x.x, x.x, q0); q1 = fmaf(x.y, x.y, q1);
        q2 = fmaf(x.z, x.z, q2); q3 = fmaf(x.w, x.w, q3);
        lcnt++;
    }
    int b = curc * 128 + chb;
    atomicAdd(&g_csum[b + 0], s0); atomicAdd(&g_csum[b + 1], s1);
    atomicAdd(&g_csum[b + 2], s2); atomicAdd(&g_csum[b + 3], s3);
    atomicAdd(&g_csumsq[b + 0], q0); atomicAdd(&g_csumsq[b + 1], q1);
    atomicAdd(&g_csumsq[b + 2], q2); atomicAdd(&g_csumsq[b + 3], q3);
    if (lane == 0) atomicAdd(&g_ccnt[curc], (unsigned)lcnt);
}

// ---- K4: finalize crystal_norm1 affine ----
__global__ void k_stats1(const float* __restrict__ gn1_g, const float* __restrict__ gn1_b) {
    int c = blockIdx.x, j = threadIdx.x;
    float cnt = fmaxf((float)g_ccnt[c], 1.f);
    float mean = g_csum[c * 128 + j] / cnt;
    float var = fmaxf(g_csumsq[c * 128 + j] / cnt - mean * mean, 0.f);
    float inv = rsqrtf(var + 1e-5f);
    float a = gn1_g[j] * inv;
    g_a1[c * 128 + j] = a;
    g_b1[c * 128 + j] = gn1_b[j] - mean * a;
}

// ---- K5a/b/c: parallel exclusive scan over counts ----
__global__ void k_scanA(int n_edges) {
    __shared__ unsigned sred[256];
    int b = blockIdx.x, t = threadIdx.x;
    int per = (n_edges + SCAN_BLOCKS - 1) / SCAN_BLOCKS;
    int s = b * per, e = min(s + per, n_edges);
    unsigned local = 0;
    for (int i = s + t; i < e; i += 256) local += g_acnt[i];
    sred[t] = local;
    __syncthreads();
    for (int off = 128; off; off >>= 1) {
        if (t < off) sred[t] += sred[t + off];
        __syncthreads();
    }
    if (t == 0) g_blksum[b] = sred[0];
}
__global__ void k_scanB(int n_edges) {
    __shared__ unsigned ss[SCAN_BLOCKS];
    int t = threadIdx.x;
    ss[t] = g_blksum[t];
    __syncthreads();
    for (int off = 1; off < SCAN_BLOCKS; off <<= 1) {
        unsigned v = (t >= off) ? ss[t - off] : 0u;
        __syncthreads();
        if (t >= off) ss[t] += v;
        __syncthreads();
    }
    g_blkoff[t] = ss[t] - g_blksum[t];
    if (t == SCAN_BLOCKS - 1) g_off[n_edges] = ss[t];
}
__global__ void k_scanC(int n_edges) {
    __shared__ unsigned ss[256];
    int b = blockIdx.x, t = threadIdx.x;
    int per = (n_edges + SCAN_BLOCKS - 1) / SCAN_BLOCKS;
    int s0 = b * per, e0 = min(s0 + per, n_edges);
    int per2 = (per + 255) / 256;
    int s = s0 + t * per2, e = min(s + per2, e0);
    unsigned local = 0;
    for (int i = s; i < e; i++) local += g_acnt[i];
    ss[t] = local;
    __syncthreads();
    for (int off = 1; off < 256; off <<= 1) {
        unsigned v = (t >= off) ? ss[t - off] : 0u;
        __syncthreads();
        if (t >= off) ss[t] += v;
        __syncthreads();
    }
    unsigned run = g_blkoff[b] + ss[t] - local;
    for (int i = s; i < e; i++) {
        unsigned c = g_acnt[i];
        g_off[i] = run;
        g_curs[i] = run;
        run += c;
    }
}

// ---- K6: fill CSR buckets, crystal id packed into high bits ----
__global__ void k_fill(const int* __restrict__ anb, const int* __restrict__ ca,
                       int n_angles) {
    int i = blockIdx.x * blockDim.x + threadIdx.x;
    if (i < n_angles) {
        int s = anb[2 * (size_t)i];
        unsigned p = atomicAdd(&g_curs[s], 1u);
        g_bucket[p] = (unsigned)i | ((unsigned)ca[i] << 24);
    }
}

// ---- K7: fused gate+gather, packed-bucket ----
__global__ void __launch_bounds__(256) k_gather(const int* __restrict__ ce,
                                                const float* __restrict__ W_mask,
                                                int n_edges) {
    int gw = blockIdx.x * (blockDim.x >> 5) + (threadIdx.x >> 5);
    int lane = threadIdx.x & 31;
    int totalw = gridDim.x * (blockDim.x >> 5);
    int chunk = (n_edges + totalw - 1) / totalw;
    int e0 = gw * chunk, eend = min(e0 + chunk, n_edges);
    if (e0 >= eend) return;
    float4 wm = make_float4(0.f, 0.f, 0.f, 0.f);
    if (lane >= 16) wm = ((const float4*)W_mask)[lane - 16];
    float4 lsum = make_float4(0.f, 0.f, 0.f, 0.f);
    float4 lsq  = make_float4(0.f, 0.f, 0.f, 0.f);
    int lcnt = 0;
    int curc = __ldg(&ce[e0]);
    for (int e = e0; e < eend; e++) {
        int c = __ldg(&ce[e]);
        if (c != curc) {
            if (lane < 16) {
                int b = curc * 64 + 4 * lane;
                atomicAdd(&g_esum[b + 0], lsum.x); atomicAdd(&g_esum[b + 1], lsum.y);
                atomicAdd(&g_esum[b + 2], lsum.z); atomicAdd(&g_esum[b + 3], lsum.w);
                atomicAdd(&g_esumsq[b + 0], lsq.x); atomicAdd(&g_esumsq[b + 1], lsq.y);
                atomicAdd(&g_esumsq[b + 2], lsq.z); atomicAdd(&g_esumsq[b + 3], lsq.w);
            }
            if (lane == 0) atomicAdd(&g_ecnt[curc], (unsigned)lcnt);
            lsum = make_float4(0.f, 0.f, 0.f, 0.f);
            lsq = make_float4(0.f, 0.f, 0.f, 0.f);
            lcnt = 0; curc = c;
        }
        unsigned s = g_off[e], t = g_off[e + 1];
        float4 acc = make_float4(0.f, 0.f, 0.f, 0.f);
        for (unsigned p = s; p < t; p += 2) {
            bool two = (p + 1 < t);
            unsigned vA = __ldg(&g_bucket[p]);
            unsigned vB = two ? __ldg(&g_bucket[p + 1]) : vA;
            int aidA = vA & 0xFFFFFFu, ccA = vA >> 24;
            int aidB = vB & 0xFFFFFFu, ccB = vB >> 24;
            float4 gA = ld_half4(&g_gbufh[(size_t)aidA * 128 + 4 * lane]);
            float4 gB = ld_half4(&g_gbufh[(size_t)aidB * 128 + 4 * lane]);
            float4 aA = *(const float4*)&g_a1[ccA * 128 + 4 * lane];
            float4 bA = *(const float4*)&g_b1[ccA * 128 + 4 * lane];
            float4 aB = *(const float4*)&g_a1[ccB * 128 + 4 * lane];
            float4 bB = *(const float4*)&g_b1[ccB * 128 + 4 * lane];
            float xA0 = fmaf(gA.x, aA.x, bA.x), xA1 = fmaf(gA.y, aA.y, bA.y);
            float xA2 = fmaf(gA.z, aA.z, bA.z), xA3 = fmaf(gA.w, aA.w, bA.w);
            float xB0 = fmaf(gB.x, aB.x, bB.x), xB1 = fmaf(gB.y, aB.y, bB.y);
            float xB2 = fmaf(gB.z, aB.z, bB.z), xB3 = fmaf(gB.w, aB.w, bB.w);
            float pA = xA0 * wm.x + xA1 * wm.y + xA2 * wm.z + xA3 * wm.w;
            float pB = xB0 * wm.x + xB1 * wm.y + xB2 * wm.z + xB3 * wm.w;
#pragma unroll
            for (int o = 16; o; o >>= 1) {
                pA += __shfl_xor_sync(0xffffffffu, pA, o);
                pB += __shfl_xor_sync(0xffffffffu, pB, o);
            }
            float fA = 1.f - 2.f / (__expf(2.f * pA) + 1.f);
            float fB = 1.f - 2.f / (__expf(2.f * pB) + 1.f);
            acc.x += fA * fmaxf(xA0, 0.f);
            acc.y += fA * fmaxf(xA1, 0.f);
            acc.z += fA * fmaxf(xA2, 0.f);
            acc.w += fA * fmaxf(xA3, 0.f);
            if (two) {
                acc.x += fB * fmaxf(xB0, 0.f);
                acc.y += fB * fmaxf(xB1, 0.f);
                acc.z += fB * fmaxf(xB2, 0.f);
                acc.w += fB * fmaxf(xB3, 0.f);
            }
        }
        float inv = 1.f / fmaxf((float)(t - s), 1.f);
        float4 v = make_float4(acc.x * inv, acc.y * inv, acc.z * inv, acc.w * inv);
        if (lane < 16) {
            *(float4*)&g_summed[(size_t)e * 64 + 4 * lane] = v;
            lsum.x += v.x; lsum.y += v.y; lsum.z += v.z; lsum.w += v.w;
            lsq.x += v.x * v.x; lsq.y += v.y * v.y; lsq.z += v.z * v.z; lsq.w += v.w * v.w;
        }
        lcnt++;
    }
    if (lane < 16) {
        int b = curc * 64 + 4 * lane;
        atomicAdd(&g_esum[b + 0], lsum.x); atomicAdd(&g_esum[b + 1], lsum.y);
        atomicAdd(&g_esum[b + 2], lsum.z); atomicAdd(&g_esum[b + 3], lsum.w);
        atomicAdd(&g_esumsq[b + 0], lsq.x); atomicAdd(&g_esumsq[b + 1], lsq.y);
        atomicAdd(&g_esumsq[b + 2], lsq.z); atomicAdd(&g_esumsq[b + 3], lsq.w);
    }
    if (lane == 0) atomicAdd(&g_ecnt[curc], (unsigned)lcnt);
}

// ---- K9: finalize crystal_norm2 affine ----
__global__ void k_stats2(const float* __restrict__ gn2_g, const float* __restrict__ gn2_b) {
    int c = blockIdx.x, j = threadIdx.x;
    float cnt = fmaxf((float)g_ecnt[c], 1.f);
    float mean = g_esum[c * 64 + j] / cnt;
    float var = fmaxf(g_esumsq[c * 64 + j] / cnt - mean * mean, 0.f);
    float inv = rsqrtf(var + 1e-5f);
    float a = gn2_g[j] * inv;
    g_a2[c * 64 + j] = a;
    g_b2[c * 64 + j] = gn2_b[j] - mean * a;
}

// ---- K10: thread-per-edge residual MLPs ----
__global__ void __launch_bounds__(256) k_final(
        const float* __restrict__ nbr, const int* __restrict__ ce,
        const float* __restrict__ W1a, const float* __restrict__ b1a,
        const float* __restrict__ W2a, const float* __restrict__ b2a,
        const float* __restrict__ W1b, const float* __restrict__ b1b,
        const float* __restrict__ W2b, const float* __restrict__ b2b,
        float* __restrict__ out, int n_edges) {
    __shared__ float4 sW1a[512], sW2a[512], sW1b[512], sW2b[512];
    __shared__ float sb1a[32], sb2a[64], sb1b[32], sb2b[64];
    int t = threadIdx.x;
    for (int k = t; k < 512; k += 256) {
        sW1a[k] = ((const float4*)W1a)[k];
        sW2a[k] = ((const float4*)W2a)[k];
        sW1b[k] = ((const float4*)W1b)[k];
        sW2b[k] = ((const float4*)W2b)[k];
    }
    if (t < 32) { sb1a[t] = b1a[t]; sb1b[t] = b1b[t]; }
    if (t < 64) { sb2a[t] = b2a[t]; sb2b[t] = b2b[t]; }
    __syncthreads();
    int e = blockIdx.x * 256 + t;
    if (e >= n_edges) return;

    float h[64];
    int c = __ldg(&ce[e]);
    {
        const float4* s4 = (const float4*)&g_summed[(size_t)e * 64];
        const float4* a4 = (const float4*)&g_a2[c * 64];
        const float4* b4 = (const float4*)&g_b2[c * 64];
#pragma unroll
        for (int i = 0; i < 16; i++) {
            float4 sv = s4[i], av = a4[i], bv = b4[i];
            h[4 * i + 0] = fmaf(sv.x, av.x, bv.x);
            h[4 * i + 1] = fmaf(sv.y, av.y, bv.y);
            h[4 * i + 2] = fmaf(sv.z, av.z, bv.z);
            h[4 * i + 3] = fmaf(sv.w, av.w, bv.w);
        }
    }
    float r[32];
    {
        ull racc[16];
#pragma unroll
        for (int j = 0; j < 16; j++) racc[j] = pack2(sb1a[2 * j], sb1a[2 * j + 1]);
#pragma unroll
        for (int k = 0; k < 64; k++) {
            ull hk = pack2(h[k], h[k]);
#pragma unroll
            for (int j = 0; j < 8; j++) {
                float4 w4 = sW1a[k * 8 + j];
                racc[2 * j]     = ffma2(hk, pack2(w4.x, w4.y), racc[2 * j]);
                racc[2 * j + 1] = ffma2(hk, pack2(w4.z, w4.w), racc[2 * j + 1]);
            }
        }
#pragma unroll
        for (int j = 0; j < 16; j++) {
            float2 u = unpack2(racc[j]);
            r[2 * j] = fmaxf(u.x, 0.f);
            r[2 * j + 1] = fmaxf(u.y, 0.f);
        }
        ull hacc[32];
#pragma unroll
        for (int j = 0; j < 32; j++) hacc[j] = pack2(h[2 * j] + sb2a[2 * j], h[2 * j + 1] + sb2a[2 * j + 1]);
#pragma unroll
        for (int k = 0; k < 32; k++) {
            ull rk = pack2(r[k], r[k]);
#pragma unroll
            for (int j = 0; j < 16; j++) {
                float4 w4 = sW2a[k * 16 + j];
                hacc[2 * j]     = ffma2(rk, pack2(w4.x, w4.y), hacc[2 * j]);
                hacc[2 * j + 1] = ffma2(rk, pack2(w4.z, w4.w), hacc[2 * j + 1]);
            }
        }
#pragma unroll
        for (int j = 0; j < 32; j++) {
            float2 u = unpack2(hacc[j]);
            h[2 * j] = u.x; h[2 * j + 1] = u.y;
        }
    }
    {
        ull racc[16];
#pragma unroll
        for (int j = 0; j < 16; j++) racc[j] = pack2(sb1b[2 * j], sb1b[2 * j + 1]);
#pragma unroll
        for (int k = 0; k < 64; k++) {
            ull hk = pack2(h[k], h[k]);
#pragma unroll
            for (int j = 0; j < 8; j++) {
                float4 w4 = sW1b[k * 8 + j];
                racc[2 * j]     = ffma2(hk, pack2(w4.x, w4.y), racc[2 * j]);
                racc[2 * j + 1] = ffma2(hk, pack2(w4.z, w4.w), racc[2 * j + 1]);
            }
        }
#pragma unroll
        for (int j = 0; j < 16; j++) {
            float2 u = unpack2(racc[j]);
            r[2 * j] = fmaxf(u.x, 0.f);
            r[2 * j + 1] = fmaxf(u.y, 0.f);
        }
        ull hacc[32];
#pragma unroll
        for (int j = 0; j < 32; j++) hacc[j] = pack2(h[2 * j] + sb2b[2 * j], h[2 * j + 1] + sb2b[2 * j + 1]);
#pragma unroll
        for (int k = 0; k < 32; k++) {
            ull rk = pack2(r[k], r[k]);
#pragma unroll
            for (int j = 0; j < 16; j++) {
                float4 w4 = sW2b[k * 16 + j];
                hacc[2 * j]     = ffma2(rk, pack2(w4.x, w4.y), hacc[2 * j]);
                hacc[2 * j + 1] = ffma2(rk, pack2(w4.z, w4.w), hacc[2 * j + 1]);
            }
        }
#pragma unroll
        for (int j = 0; j < 32; j++) {
            float2 u = unpack2(hacc[j]);
            h[2 * j] = u.x; h[2 * j + 1] = u.y;
        }
    }
    {
        const float4* n4 = (const float4*)&nbr[(size_t)e * 64];
        float4* o4 = (float4*)&out[(size_t)e * 64];
#pragma unroll
        for (int i = 0; i < 16; i++) {
            float4 nv = n4[i];
            float4 ov;
            ov.x = 0.7071067811865476f * fmaxf(nv.x + h[4 * i + 0], 0.f);
            ov.y = 0.7071067811865476f * fmaxf(nv.y + h[4 * i + 1], 0.f);
            ov.z = 0.7071067811865476f * fmaxf(nv.z + h[4 * i + 2], 0.f);
            ov.w = 0.7071067811865476f * fmaxf(nv.w + h[4 * i + 3], 0.f);
            o4[i] = ov;
        }
    }
}

extern "C" void kernel_launch(void* const* d_in, const int* in_sizes, int n_in,
                              void* d_out, int out_size) {
    const float* nbr       = (const float*)d_in[0];
    const float* angle_fea = (const float*)d_in[1];
    const int*   anb       = (const int*)d_in[2];
    const int*   ce        = (const int*)d_in[3];
    const int*   ca        = (const int*)d_in[4];
    const float* W_full    = (const float*)d_in[5];
    const float* W_mask    = (const float*)d_in[6];
    const float* gn1_g     = (const float*)d_in[7];
    const float* gn1_b     = (const float*)d_in[8];
    const float* gn2_g     = (const float*)d_in[9];
    const float* gn2_b     = (const float*)d_in[10];
    const float* W1a       = (const float*)d_in[11];
    const float* b1a       = (const float*)d_in[12];
    const float* W2a       = (const float*)d_in[13];
    const float* b2a       = (const float*)d_in[14];
    const float* W1b       = (const float*)d_in[15];
    const float* b1b       = (const float*)d_in[16];
    const float* W2b       = (const float*)d_in[17];
    const float* b2b       = (const float*)d_in[18];
    float* out = (float*)d_out;

    int n_edges  = in_sizes[0] / 64;
    int n_angles = in_sizes[1] / 40;

    k_zero<<<512, 256>>>(n_edges);
    dim3 g1(1024, 2);
    k_precompute<<<g1, 128>>>(nbr, W_full, n_edges);
    k_count<<<(n_angles + 255) / 256, 256>>>(anb, n_angles);
    k_scanA<<<SCAN_BLOCKS, 256>>>(n_edges);
    k_scanB<<<1, SCAN_BLOCKS>>>(n_edges);
    k_scanC<<<SCAN_BLOCKS, 256>>>(n_edges);
    k_fill<<<(n_angles + 255) / 256, 256>>>(anb, ca, n_angles);
    int nblk = 4096;
    int chunk = ((n_angles + nblk - 1) / nblk + ATILE - 1) / ATILE * ATILE;
    k_angle_mma<<<nblk, 128>>>(angle_fea, anb, W_full, n_angles, chunk);
    k_stats_g<<<2048, 256>>>(ca, n_angles);
    k_stats1<<<256, 128>>>(gn1_g, gn1_b);
    k_gather<<<2048, 256>>>(ce, W_mask, n_edges);
    k_stats2<<<256, 64>>>(gn2_g, gn2_b);
    k_final<<<(n_edges + 255) / 256, 256>>>(nbr, ce, W1a, b1a, W2a, b2a,
                                            W1b, b1b, W2b, b2b, out, n_edges);
}

// round 13
// speedup vs baseline: 1.2502x; 1.0533x over previous
#include <cuda_runtime.h>
#include <cuda_fp16.h>
#include <math.h>

#define NE_MAX 200000
#define NA_MAX 1600000
#define ATILE 32
#define SCAN_BLOCKS 256
#define SP_STRIDE 136

// ---- static scratch ----
__device__ __half g_P0h[(size_t)NE_MAX * 128];
__device__ __half g_P1h[(size_t)NE_MAX * 128];
__device__ __half g_gbufh[(size_t)NA_MAX * 128];
__device__ float g_csum[256 * 128];
__device__ float g_csumsq[256 * 128];
__device__ int g_cbound[257];
__device__ int g_ebound[257];
__device__ float g_a1[256 * 128];
__device__ float g_b1[256 * 128];
__device__ float g_summed[(size_t)NE_MAX * 64];
__device__ unsigned g_acnt[NE_MAX];
__device__ unsigned g_off[NE_MAX + 1];
__device__ unsigned g_curs[NE_MAX];
__device__ unsigned g_bucket[NA_MAX];   // aid | (crystal << 24)
__device__ unsigned g_blksum[SCAN_BLOCKS];
__device__ unsigned g_blkoff[SCAN_BLOCKS];
__device__ float g_esum[256 * 64];
__device__ float g_esumsq[256 * 64];
__device__ float g_a2[256 * 64];
__device__ float g_b2[256 * 64];

typedef unsigned long long ull;
__device__ __forceinline__ ull ffma2(ull a, ull b, ull c) {
    ull d; asm("fma.rn.f32x2 %0, %1, %2, %3;" : "=l"(d) : "l"(a), "l"(b), "l"(c)); return d;
}
__device__ __forceinline__ ull addf2(ull a, ull b) {
    ull d; asm("add.rn.f32x2 %0, %1, %2;" : "=l"(d) : "l"(a), "l"(b)); return d;
}
__device__ __forceinline__ ull pack2(float x, float y) {
    ull d; asm("mov.b64 %0, {%1, %2};" : "=l"(d) : "f"(x), "f"(y)); return d;
}
__device__ __forceinline__ float2 unpack2(ull a) {
    float x, y; asm("mov.b64 {%0, %1}, %2;" : "=f"(x), "=f"(y) : "l"(a));
    return make_float2(x, y);
}
__device__ __forceinline__ float4 ld_half4(const __half* p) {
    uint2 u = *(const uint2*)p;
    float2 fa = __half22float2(*(__half2*)&u.x);
    float2 fb = __half22float2(*(__half2*)&u.y);
    return make_float4(fa.x, fa.y, fb.x, fb.y);
}
__device__ __forceinline__ void cp_async8(void* smem, const void* gmem) {
    unsigned s = (unsigned)__cvta_generic_to_shared(smem);
    asm volatile("cp.async.ca.shared.global [%0], [%1], 8;" :: "r"(s), "l"(gmem));
}
__device__ __forceinline__ void cp_async16(void* smem, const void* gmem) {
    unsigned s = (unsigned)__cvta_generic_to_shared(smem);
    asm volatile("cp.async.cg.shared.global [%0], [%1], 16;" :: "r"(s), "l"(gmem));
}
__device__ __forceinline__ void cp_async4(void* smem, const void* gmem) {
    unsigned s = (unsigned)__cvta_generic_to_shared(smem);
    asm volatile("cp.async.ca.shared.global [%0], [%1], 4;" :: "r"(s), "l"(gmem));
}
__device__ __forceinline__ void cp_commit() { asm volatile("cp.async.commit_group;" ::: "memory"); }
template <int N>
__device__ __forceinline__ void cp_wait() { asm volatile("cp.async.wait_group %0;" :: "n"(N) : "memory"); }
__device__ __forceinline__ void mma_16816(float c[4], unsigned a0, unsigned a1,
                                          unsigned a2, unsigned a3,
                                          unsigned b0, unsigned b1) {
    asm volatile(
        "mma.sync.aligned.m16n8k16.row.col.f32.f16.f16.f32 "
        "{%0,%1,%2,%3}, {%4,%5,%6,%7}, {%8,%9}, {%0,%1,%2,%3};"
        : "+f"(c[0]), "+f"(c[1]), "+f"(c[2]), "+f"(c[3])
        : "r"(a0), "r"(a1), "r"(a2), "r"(a3), "r"(b0), "r"(b1));
}

// ---- K0: zero accumulators ----
__global__ void k_zero(int n_edges) {
    int i = blockIdx.x * blockDim.x + threadIdx.x;
    int stride = gridDim.x * blockDim.x;
    for (int k = i; k < n_edges; k += stride) g_acnt[k] = 0u;
    for (int k = i; k < 256 * 128; k += stride) { g_csum[k] = 0.f; g_csumsq[k] = 0.f; }
    for (int k = i; k < 256 * 64; k += stride) { g_esum[k] = 0.f; g_esumsq[k] = 0.f; }
}

// ---- K0b: per-crystal segment bounds via binary search (ca, ce sorted) ----
__global__ void k_bounds(const int* __restrict__ ca, const int* __restrict__ ce,
                         int n_angles, int n_edges) {
    int c = threadIdx.x;  // 0..255
    int lo = 0, hi = n_angles;
    while (lo < hi) { int mid = (lo + hi) >> 1; if (__ldg(&ca[mid]) < c) lo = mid + 1; else hi = mid; }
    g_cbound[c] = lo;
    lo = 0; hi = n_edges;
    while (lo < hi) { int mid = (lo + hi) >> 1; if (__ldg(&ce[mid]) < c) lo = mid + 1; else hi = mid; }
    g_ebound[c] = lo;
    if (c == 0) { g_cbound[256] = n_angles; g_ebound[256] = n_edges; }
}

// ---- K1: P0/P1 = nbr_fea @ W_full halves (fp16 out, k-packed FFMA2) ----
__global__ void __launch_bounds__(128) k_precompute(
        const float* __restrict__ nbr, const float* __restrict__ W_full, int n_edges) {
    int j = threadIdx.x;
    int half = blockIdx.y;
    ull w2[32];
    const float* wb = W_full + (size_t)(40 + half * 64) * 128 + j;
#pragma unroll
    for (int kk = 0; kk < 32; kk++)
        w2[kk] = pack2(wb[(size_t)(2 * kk) * 128], wb[(size_t)(2 * kk + 1) * 128]);
    __half* P = half ? g_P1h : g_P0h;
    __shared__ __align__(16) ull snb[2][32];
    int nb = gridDim.x;
    for (int e2 = blockIdx.x * 2; e2 < n_edges; e2 += nb * 2) {
        if (j < 64) {
            int g = j >> 5, jj = j & 31;
            int e = min(e2 + g, n_edges - 1);
            snb[g][jj] = ((const ull*)(nbr + (size_t)e * 64))[jj];
        }
        __syncthreads();
#pragma unroll 2
        for (int gg = 0; gg < 2; gg++) {
            int ee = e2 + gg;
            if (ee >= n_edges) break;
            ull acc = 0ull;
#pragma unroll
            for (int kk = 0; kk < 16; kk++) {
                ulonglong2 v = *(const ulonglong2*)&snb[gg][2 * kk];
                acc = ffma2(v.x, w2[2 * kk], acc);
                acc = ffma2(v.y, w2[2 * kk + 1], acc);
            }
            float2 u = unpack2(acc);
            P[(size_t)ee * 128 + j] = __float2half_rn(u.x + u.y);
        }
        __syncthreads();
    }
}

// ---- K2: count angles per src edge ----
__global__ void k_count(const int* __restrict__ anb, int n_angles) {
    int i = blockIdx.x * blockDim.x + threadIdx.x;
    if (i < n_angles) atomicAdd(&g_acnt[anb[2 * (size_t)i]], 1u);
}

// ---- K3: angle GEMM via HMMA; smem-staged P; register-resident norm1 stats ----
__global__ void __launch_bounds__(128) k_angle_mma(
        const float* __restrict__ af, const int* __restrict__ anb,
        const int* __restrict__ ca, const float* __restrict__ W,
        int n_angles, int chunk) {
    int tid = threadIdx.x;
    int wid = tid >> 5, lane = tid & 31;
    int g = lane >> 2, t = lane & 3;
    int nbase = wid * 32;

    unsigned bfrag[4][3][2];
#pragma unroll
    for (int nt = 0; nt < 4; nt++)
#pragma unroll
        for (int ks = 0; ks < 3; ks++) {
            int ch = nbase + nt * 8 + g;
            int k0 = ks * 16 + 2 * t;
            float w00 = (k0 < 40)     ? __ldg(&W[(size_t)k0 * 128 + ch]) : 0.f;
            float w01 = (k0 + 1 < 40) ? __ldg(&W[(size_t)(k0 + 1) * 128 + ch]) : 0.f;
            float w10 = (k0 + 8 < 40) ? __ldg(&W[(size_t)(k0 + 8) * 128 + ch]) : 0.f;
            float w11 = (k0 + 9 < 40) ? __ldg(&W[(size_t)(k0 + 9) * 128 + ch]) : 0.f;
            __half2 h0 = __floats2half2_rn(w00, w01);
            __half2 h1 = __floats2half2_rn(w10, w11);
            bfrag[nt][ks][0] = *(unsigned*)&h0;
            bfrag[nt][ks][1] = *(unsigned*)&h1;
        }

    __shared__ __align__(16) ull s_af[2][ATILE * 20];
    __shared__ int s_ii[2][ATILE * 2];
    __shared__ int s_ca[2][ATILE];
    __shared__ __align__(16) __half sAh[32][56];
    __shared__ __align__(16) __half sP[64][SP_STRIDE];

    for (int idx = tid; idx < 32 * 16; idx += 128)
        sAh[idx >> 4][40 + (idx & 15)] = __float2half(0.f);

    int a0 = blockIdx.x * chunk;
    int aend = min(a0 + chunk, n_angles);
    if (a0 >= aend) return;

    const ull* af2 = (const ull*)af;
    int maxf2 = n_angles * 20 - 1;
    int maxi  = n_angles - 1;

    {
#pragma unroll
        for (int r = 0; r < 5; r++) {
            int pos = r * 128 + tid;
            cp_async8(&s_af[0][pos], &af2[min(a0 * 20 + pos, maxf2)]);
        }
        if (tid < 64) cp_async4(&s_ii[0][tid], &anb[min(2 * a0 + tid, 2 * maxi + 1)]);
        else if (tid < 96) cp_async4(&s_ca[0][tid - 64], &ca[min(a0 + tid - 64, maxi)]);
        cp_commit();
    }

    // per-thread norm1 stats accumulators (4 nt x 2 channels, packed f32x2)
    ull zsum[4] = {0ull, 0ull, 0ull, 0ull};
    ull zsq[4]  = {0ull, 0ull, 0ull, 0ull};
    int curc = -1;

    int buf = 0;
    for (int base = a0; base < aend; base += ATILE, buf ^= 1) {
        int nbase2 = base + ATILE;
        bool has_next = nbase2 < aend;
        cp_wait<0>();
        __syncthreads();

#pragma unroll
        for (int q = 0; q < 8; q++) {
            int cidx = q * 128 + tid;
            int row = cidx >> 4;
            int off = (cidx & 15) * 8;
            int idx = (row < 32) ? s_ii[buf][2 * row] : s_ii[buf][2 * (row - 32) + 1];
            const __half* src = (row < 32) ? &g_P0h[(size_t)idx * 128 + off]
                                           : &g_P1h[(size_t)idx * 128 + off];
            cp_async16(&sP[row][off], src);
        }
        cp_commit();

        if (has_next) {
#pragma unroll
            for (int r = 0; r < 5; r++) {
                int pos = r * 128 + tid;
                cp_async8(&s_af[buf ^ 1][pos], &af2[min(nbase2 * 20 + pos, maxf2)]);
            }
            if (tid < 64) cp_async4(&s_ii[buf ^ 1][tid], &anb[min(2 * nbase2 + tid, 2 * maxi + 1)]);
            else if (tid < 96) cp_async4(&s_ca[buf ^ 1][tid - 64], &ca[min(nbase2 + tid - 64, maxi)]);
            cp_commit();
        }

        const float* afv = (const float*)s_af[buf];
#pragma unroll
        for (int q = 0; q < 10; q++) {
            int idx = q * 128 + tid;
            sAh[idx / 40][idx % 40] = __float2half_rn(afv[idx]);
        }
        if (has_next) cp_wait<1>(); else cp_wait<0>();
        __syncthreads();

#pragma unroll
        for (int mt = 0; mt < 2; mt++) {
            int rA = mt * 16 + g;
            int rB = rA + 8;
            float c[4][4];
#pragma unroll
            for (int nt = 0; nt < 4; nt++)
#pragma unroll
                for (int q = 0; q < 4; q++) c[nt][q] = 0.f;
#pragma unroll
            for (int ks = 0; ks < 3; ks++) {
                unsigned a0f = *(const unsigned*)&sAh[rA][ks * 16 + 2 * t];
                unsigned a1f = *(const unsigned*)&sAh[rB][ks * 16 + 2 * t];
                unsigned a2f = *(const unsigned*)&sAh[rA][ks * 16 + 2 * t + 8];
                unsigned a3f = *(const unsigned*)&sAh[rB][ks * 16 + 2 * t + 8];
#pragma unroll
                for (int nt = 0; nt < 4; nt++)
                    mma_16816(c[nt], a0f, a1f, a2f, a3f,
                              bfrag[nt][ks][0], bfrag[nt][ks][1]);
            }
            int angleA = base + rA;
            int angleB = base + rB;
            ull xpA[4], xpB[4];
#pragma unroll
            for (int nt = 0; nt < 4; nt++) {
                int ch = nbase + nt * 8 + 2 * t;
                float2 q0A = __half22float2(*(const __half2*)&sP[rA][ch]);
                float2 q1A = __half22float2(*(const __half2*)&sP[32 + rA][ch]);
                float xA0 = c[nt][0] + q0A.x + q1A.x;
                float xA1 = c[nt][1] + q0A.y + q1A.y;
                xpA[nt] = pack2(xA0, xA1);
                float2 q0B = __half22float2(*(const __half2*)&sP[rB][ch]);
                float2 q1B = __half22float2(*(const __half2*)&sP[32 + rB][ch]);
                float xB0 = c[nt][2] + q0B.x + q1B.x;
                float xB1 = c[nt][3] + q0B.y + q1B.y;
                xpB[nt] = pack2(xB0, xB1);
                if (angleA < aend)
                    *(__half2*)&g_gbufh[(size_t)angleA * 128 + ch] = __floats2half2_rn(xA0, xA1);
                if (angleB < aend)
                    *(__half2*)&g_gbufh[(size_t)angleB * 128 + ch] = __floats2half2_rn(xB0, xB1);
            }
            // ---- register-resident stats (rows processed in increasing angle order) ----
            if (angleA < aend) {
                int cA = s_ca[buf][rA];
                if (cA != curc) {
                    if (curc >= 0) {
#pragma unroll
                        for (int nt = 0; nt < 4; nt++) {
                            int ch = nbase + nt * 8 + 2 * t;
                            float2 us = unpack2(zsum[nt]), uq = unpack2(zsq[nt]);
                            atomicAdd(&g_csum[curc * 128 + ch], us.x);
                            atomicAdd(&g_csum[curc * 128 + ch + 1], us.y);
                            atomicAdd(&g_csumsq[curc * 128 + ch], uq.x);
                            atomicAdd(&g_csumsq[curc * 128 + ch + 1], uq.y);
                            zsum[nt] = 0ull; zsq[nt] = 0ull;
                        }
                    }
                    curc = cA;
                }
#pragma unroll
                for (int nt = 0; nt < 4; nt++) {
                    zsum[nt] = addf2(zsum[nt], xpA[nt]);
                    zsq[nt] = ffma2(xpA[nt], xpA[nt], zsq[nt]);
                }
            }
            if (angleB < aend) {
                int cB = s_ca[buf][rB];
                if (cB != curc) {
                    if (curc >= 0) {
#pragma unroll
                        for (int nt = 0; nt < 4; nt++) {
                            int ch = nbase + nt * 8 + 2 * t;
                            float2 us = unpack2(zsum[nt]), uq = unpack2(zsq[nt]);
                            atomicAdd(&g_csum[curc * 128 + ch], us.x);
                            atomicAdd(&g_csum[curc * 128 + ch + 1], us.y);
                            atomicAdd(&g_csumsq[curc * 128 + ch], uq.x);
                            atomicAdd(&g_csumsq[curc * 128 + ch + 1], uq.y);
                            zsum[nt] = 0ull; zsq[nt] = 0ull;
                        }
                    }
                    curc = cB;
                }
#pragma unroll
                for (int nt = 0; nt < 4; nt++) {
                    zsum[nt] = addf2(zsum[nt], xpB[nt]);
                    zsq[nt] = ffma2(xpB[nt], xpB[nt], zsq[nt]);
                }
            }
        }
        __syncthreads();
    }
    if (curc >= 0) {
#pragma unroll
        for (int nt = 0; nt < 4; nt++) {
            int ch = nbase + nt * 8 + 2 * t;
            float2 us = unpack2(zsum[nt]), uq = unpack2(zsq[nt]);
            atomicAdd(&g_csum[curc * 128 + ch], us.x);
            atomicAdd(&g_csum[curc * 128 + ch + 1], us.y);
            atomicAdd(&g_csumsq[curc * 128 + ch], uq.x);
            atomicAdd(&g_csumsq[curc * 128 + ch + 1], uq.y);
        }
    }
}

// ---- K4: finalize crystal_norm1 affine (counts from binary-search bounds) ----
__global__ void k_stats1(const float* __restrict__ gn1_g, const float* __restrict__ gn1_b) {
    int c = blockIdx.x, j = threadIdx.x;
    float cnt = fmaxf((float)(g_cbound[c + 1] - g_cbound[c]), 1.f);
    float mean = g_csum[c * 128 + j] / cnt;
    float var = fmaxf(g_csumsq[c * 128 + j] / cnt - mean * mean, 0.f);
    float inv = rsqrtf(var + 1e-5f);
    float a = gn1_g[j] * inv;
    g_a1[c * 128 + j] = a;
    g_b1[c * 128 + j] = gn1_b[j] - mean * a;
}

// ---- K5a/b/c: parallel exclusive scan over counts ----
__global__ void k_scanA(int n_edges) {
    __shared__ unsigned sred[256];
    int b = blockIdx.x, t = threadIdx.x;
    int per = (n_edges + SCAN_BLOCKS - 1) / SCAN_BLOCKS;
    int s = b * per, e = min(s + per, n_edges);
    unsigned local = 0;
    for (int i = s + t; i < e; i += 256) local += g_acnt[i];
    sred[t] = local;
    __syncthreads();
    for (int off = 128; off; off >>= 1) {
        if (t < off) sred[t] += sred[t + off];
        __syncthreads();
    }
    if (t == 0) g_blksum[b] = sred[0];
}
__global__ void k_scanB(int n_edges) {
    __shared__ unsigned ss[SCAN_BLOCKS];
    int t = threadIdx.x;
    ss[t] = g_blksum[t];
    __syncthreads();
    for (int off = 1; off < SCAN_BLOCKS; off <<= 1) {
        unsigned v = (t >= off) ? ss[t - off] : 0u;
        __syncthreads();
        if (t >= off) ss[t] += v;
        __syncthreads();
    }
    g_blkoff[t] = ss[t] - g_blksum[t];
    if (t == SCAN_BLOCKS - 1) g_off[n_edges] = ss[t];
}
__global__ void k_scanC(int n_edges) {
    __shared__ unsigned ss[256];
    int b = blockIdx.x, t = threadIdx.x;
    int per = (n_edges + SCAN_BLOCKS - 1) / SCAN_BLOCKS;
    int s0 = b * per, e0 = min(s0 + per, n_edges);
    int per2 = (per + 255) / 256;
    int s = s0 + t * per2, e = min(s + per2, e0);
    unsigned local = 0;
    for (int i = s; i < e; i++) local += g_acnt[i];
    ss[t] = local;
    __syncthreads();
    for (int off = 1; off < 256; off <<= 1) {
        unsigned v = (t >= off) ? ss[t - off] : 0u;
        __syncthreads();
        if (t >= off) ss[t] += v;
        __syncthreads();
    }
    unsigned run = g_blkoff[b] + ss[t] - local;
    for (int i = s; i < e; i++) {
        unsigned c = g_acnt[i];
        g_off[i] = run;
        g_curs[i] = run;
        run += c;
    }
}

// ---- K6: fill CSR buckets, crystal id packed into high bits ----
__global__ void k_fill(const int* __restrict__ anb, const int* __restrict__ ca,
                       int n_angles) {
    int i = blockIdx.x * blockDim.x + threadIdx.x;
    if (i < n_angles) {
        int s = anb[2 * (size_t)i];
        unsigned p = atomicAdd(&g_curs[s], 1u);
        g_bucket[p] = (unsigned)i | ((unsigned)ca[i] << 24);
    }
}

// ---- K7: fused gate+gather, packed-bucket ----
__global__ void __launch_bounds__(256) k_gather(const int* __restrict__ ce,
                                                const float* __restrict__ W_mask,
                                                int n_edges) {
    int gw = blockIdx.x * (blockDim.x >> 5) + (threadIdx.x >> 5);
    int lane = threadIdx.x & 31;
    int totalw = gridDim.x * (blockDim.x >> 5);
    int chunk = (n_edges + totalw - 1) / totalw;
    int e0 = gw * chunk, eend = min(e0 + chunk, n_edges);
    if (e0 >= eend) return;
    float4 wm = make_float4(0.f, 0.f, 0.f, 0.f);
    if (lane >= 16) wm = ((const float4*)W_mask)[lane - 16];
    float4 lsum = make_float4(0.f, 0.f, 0.f, 0.f);
    float4 lsq  = make_float4(0.f, 0.f, 0.f, 0.f);
    int curc = __ldg(&ce[e0]);
    for (int e = e0; e < eend; e++) {
        int c = __ldg(&ce[e]);
        if (c != curc) {
            if (lane < 16) {
                int b = curc * 64 + 4 * lane;
                atomicAdd(&g_esum[b + 0], lsum.x); atomicAdd(&g_esum[b + 1], lsum.y);
                atomicAdd(&g_esum[b + 2], lsum.z); atomicAdd(&g_esum[b + 3], lsum.w);
                atomicAdd(&g_esumsq[b + 0], lsq.x); atomicAdd(&g_esumsq[b + 1], lsq.y);
                atomicAdd(&g_esumsq[b + 2], lsq.z); atomicAdd(&g_esumsq[b + 3], lsq.w);
            }
            lsum = make_float4(0.f, 0.f, 0.f, 0.f);
            lsq = make_float4(0.f, 0.f, 0.f, 0.f);
            curc = c;
        }
        unsigned s = g_off[e], t = g_off[e + 1];
        float4 acc = make_float4(0.f, 0.f, 0.f, 0.f);
        for (unsigned p = s; p < t; p += 2) {
            bool two = (p + 1 < t);
            unsigned vA = __ldg(&g_bucket[p]);
            unsigned vB = two ? __ldg(&g_bucket[p + 1]) : vA;
            int aidA = vA & 0xFFFFFFu, ccA = vA >> 24;
            int aidB = vB & 0xFFFFFFu, ccB = vB >> 24;
            float4 gA = ld_half4(&g_gbufh[(size_t)aidA * 128 + 4 * lane]);
            float4 gB = ld_half4(&g_gbufh[(size_t)aidB * 128 + 4 * lane]);
            float4 aA = *(const float4*)&g_a1[ccA * 128 + 4 * lane];
            float4 bA = *(const float4*)&g_b1[ccA * 128 + 4 * lane];
            float4 aB = *(const float4*)&g_a1[ccB * 128 + 4 * lane];
            float4 bB = *(const float4*)&g_b1[ccB * 128 + 4 * lane];
            float xA0 = fmaf(gA.x, aA.x, bA.x), xA1 = fmaf(gA.y, aA.y, bA.y);
            float xA2 = fmaf(gA.z, aA.z, bA.z), xA3 = fmaf(gA.w, aA.w, bA.w);
            float xB0 = fmaf(gB.x, aB.x, bB.x), xB1 = fmaf(gB.y, aB.y, bB.y);
            float xB2 = fmaf(gB.z, aB.z, bB.z), xB3 = fmaf(gB.w, aB.w, bB.w);
            float pA = xA0 * wm.x + xA1 * wm.y + xA2 * wm.z + xA3 * wm.w;
            float pB = xB0 * wm.x + xB1 * wm.y + xB2 * wm.z + xB3 * wm.w;
#pragma unroll
            for (int o = 16; o; o >>= 1) {
                pA += __shfl_xor_sync(0xffffffffu, pA, o);
                pB += __shfl_xor_sync(0xffffffffu, pB, o);
            }
            float fA = 1.f - 2.f / (__expf(2.f * pA) + 1.f);
            float fB = 1.f - 2.f / (__expf(2.f * pB) + 1.f);
            acc.x += fA * fmaxf(xA0, 0.f);
            acc.y += fA * fmaxf(xA1, 0.f);
            acc.z += fA * fmaxf(xA2, 0.f);
            acc.w += fA * fmaxf(xA3, 0.f);
            if (two) {
                acc.x += fB * fmaxf(xB0, 0.f);
                acc.y += fB * fmaxf(xB1, 0.f);
                acc.z += fB * fmaxf(xB2, 0.f);
                acc.w += fB * fmaxf(xB3, 0.f);
            }
        }
        float inv = 1.f / fmaxf((float)(t - s), 1.f);
        float4 v = make_float4(acc.x * inv, acc.y * inv, acc.z * inv, acc.w * inv);
        if (lane < 16) {
            *(float4*)&g_summed[(size_t)e * 64 + 4 * lane] = v;
            lsum.x += v.x; lsum.y += v.y; lsum.z += v.z; lsum.w += v.w;
            lsq.x += v.x * v.x; lsq.y += v.y * v.y; lsq.z += v.z * v.z; lsq.w += v.w * v.w;
        }
    }
    if (lane < 16) {
        int b = curc * 64 + 4 * lane;
        atomicAdd(&g_esum[b + 0], lsum.x); atomicAdd(&g_esum[b + 1], lsum.y);
        atomicAdd(&g_esum[b + 2], lsum.z); atomicAdd(&g_esum[b + 3], lsum.w);
        atomicAdd(&g_esumsq[b + 0], lsq.x); atomicAdd(&g_esumsq[b + 1], lsq.y);
        atomicAdd(&g_esumsq[b + 2], lsq.z); atomicAdd(&g_esumsq[b + 3], lsq.w);
    }
}

// ---- K9: finalize crystal_norm2 affine (counts from bounds) ----
__global__ void k_stats2(const float* __restrict__ gn2_g, const float* __restrict__ gn2_b) {
    int c = blockIdx.x, j = threadIdx.x;
    float cnt = fmaxf((float)(g_ebound[c + 1] - g_ebound[c]), 1.f);
    float mean = g_esum[c * 64 + j] / cnt;
    float var = fmaxf(g_esumsq[c * 64 + j] / cnt - mean * mean, 0.f);
    float inv = rsqrtf(var + 1e-5f);
    float a = gn2_g[j] * inv;
    g_a2[c * 64 + j] = a;
    g_b2[c * 64 + j] = gn2_b[j] - mean * a;
}

// ---- K10: thread-per-edge residual MLPs ----
__global__ void __launch_bounds__(256) k_final(
        const float* __restrict__ nbr, const int* __restrict__ ce,
        const float* __restrict__ W1a, const float* __restrict__ b1a,
        const float* __restrict__ W2a, const float* __restrict__ b2a,
        const float* __restrict__ W1b, const float* __restrict__ b1b,
        const float* __restrict__ W2b, const float* __restrict__ b2b,
        float* __restrict__ out, int n_edges) {
    __shared__ float4 sW1a[512], sW2a[512], sW1b[512], sW2b[512];
    __shared__ float sb1a[32], sb2a[64], sb1b[32], sb2b[64];
    int t = threadIdx.x;
    for (int k = t; k < 512; k += 256) {
        sW1a[k] = ((const float4*)W1a)[k];
        sW2a[k] = ((const float4*)W2a)[k];
        sW1b[k] = ((const float4*)W1b)[k];
        sW2b[k] = ((const float4*)W2b)[k];
    }
    if (t < 32) { sb1a[t] = b1a[t]; sb1b[t] = b1b[t]; }
    if (t < 64) { sb2a[t] = b2a[t]; sb2b[t] = b2b[t]; }
    __syncthreads();
    int e = blockIdx.x * 256 + t;
    if (e >= n_edges) return;

    float h[64];
    int c = __ldg(&ce[e]);
    {
        const float4* s4 = (const float4*)&g_summed[(size_t)e * 64];
        const float4* a4 = (const float4*)&g_a2[c * 64];
        const float4* b4 = (const float4*)&g_b2[c * 64];
#pragma unroll
        for (int i = 0; i < 16; i++) {
            float4 sv = s4[i], av = a4[i], bv = b4[i];
            h[4 * i + 0] = fmaf(sv.x, av.x, bv.x);
            h[4 * i + 1] = fmaf(sv.y, av.y, bv.y);
            h[4 * i + 2] = fmaf(sv.z, av.z, bv.z);
            h[4 * i + 3] = fmaf(sv.w, av.w, bv.w);
        }
    }
    float r[32];
    {
        ull racc[16];
#pragma unroll
        for (int j = 0; j < 16; j++) racc[j] = pack2(sb1a[2 * j], sb1a[2 * j + 1]);
#pragma unroll
        for (int k = 0; k < 64; k++) {
            ull hk = pack2(h[k], h[k]);
#pragma unroll
            for (int j = 0; j < 8; j++) {
                float4 w4 = sW1a[k * 8 + j];
                racc[2 * j]     = ffma2(hk, pack2(w4.x, w4.y), racc[2 * j]);
                racc[2 * j + 1] = ffma2(hk, pack2(w4.z, w4.w), racc[2 * j + 1]);
            }
        }
#pragma unroll
        for (int j = 0; j < 16; j++) {
            float2 u = unpack2(racc[j]);
            r[2 * j] = fmaxf(u.x, 0.f);
            r[2 * j + 1] = fmaxf(u.y, 0.f);
        }
        ull hacc[32];
#pragma unroll
        for (int j = 0; j < 32; j++) hacc[j] = pack2(h[2 * j] + sb2a[2 * j], h[2 * j + 1] + sb2a[2 * j + 1]);
#pragma unroll
        for (int k = 0; k < 32; k++) {
            ull rk = pack2(r[k], r[k]);
#pragma unroll
            for (int j = 0; j < 16; j++) {
                float4 w4 = sW2a[k * 16 + j];
                hacc[2 * j]     = ffma2(rk, pack2(w4.x, w4.y), hacc[2 * j]);
                hacc[2 * j + 1] = ffma2(rk, pack2(w4.z, w4.w), hacc[2 * j + 1]);
            }
        }
#pragma unroll
        for (int j = 0; j < 32; j++) {
            float2 u = unpack2(hacc[j]);
            h[2 * j] = u.x; h[2 * j + 1] = u.y;
        }
    }
    {
        ull racc[16];
#pragma unroll
        for (int j = 0; j < 16; j++) racc[j] = pack2(sb1b[2 * j], sb1b[2 * j + 1]);
#pragma unroll
        for (int k = 0; k < 64; k++) {
            ull hk = pack2(h[k], h[k]);
#pragma unroll
            for (int j = 0; j < 8; j++) {
                float4 w4 = sW1b[k * 8 + j];
                racc[2 * j]     = ffma2(hk, pack2(w4.x, w4.y), racc[2 * j]);
                racc[2 * j + 1] = ffma2(hk, pack2(w4.z, w4.w), racc[2 * j + 1]);
            }
        }
#pragma unroll
        for (int j = 0; j < 16; j++) {
            float2 u = unpack2(racc[j]);
            r[2 * j] = fmaxf(u.x, 0.f);
            r[2 * j + 1] = fmaxf(u.y, 0.f);
        }
        ull hacc[32];
#pragma unroll
        for (int j = 0; j < 32; j++) hacc[j] = pack2(h[2 * j] + sb2b[2 * j], h[2 * j + 1] + sb2b[2 * j + 1]);
#pragma unroll
        for (int k = 0; k < 32; k++) {
            ull rk = pack2(r[k], r[k]);
#pragma unroll
            for (int j = 0; j < 16; j++) {
                float4 w4 = sW2b[k * 16 + j];
                hacc[2 * j]     = ffma2(rk, pack2(w4.x, w4.y), hacc[2 * j]);
                hacc[2 * j + 1] = ffma2(rk, pack2(w4.z, w4.w), hacc[2 * j + 1]);
            }
        }
#pragma unroll
        for (int j = 0; j < 32; j++) {
            float2 u = unpack2(hacc[j]);
            h[2 * j] = u.x; h[2 * j + 1] = u.y;
        }
    }
    {
        const float4* n4 = (const float4*)&nbr[(size_t)e * 64];
        float4* o4 = (float4*)&out[(size_t)e * 64];
#pragma unroll
        for (int i = 0; i < 16; i++) {
            float4 nv = n4[i];
            float4 ov;
            ov.x = 0.7071067811865476f * fmaxf(nv.x + h[4 * i + 0], 0.f);
            ov.y = 0.7071067811865476f * fmaxf(nv.y + h[4 * i + 1], 0.f);
            ov.z = 0.7071067811865476f * fmaxf(nv.z + h[4 * i + 2], 0.f);
            ov.w = 0.7071067811865476f * fmaxf(nv.w + h[4 * i + 3], 0.f);
            o4[i] = ov;
        }
    }
}

extern "C" void kernel_launch(void* const* d_in, const int* in_sizes, int n_in,
                              void* d_out, int out_size) {
    const float* nbr       = (const float*)d_in[0];
    const float* angle_fea = (const float*)d_in[1];
    const int*   anb       = (const int*)d_in[2];
    const int*   ce        = (const int*)d_in[3];
    const int*   ca        = (const int*)d_in[4];
    const float* W_full    = (const float*)d_in[5];
    const float* W_mask    = (const float*)d_in[6];
    const float* gn1_g     = (const float*)d_in[7];
    const float* gn1_b     = (const float*)d_in[8];
    const float* gn2_g     = (const float*)d_in[9];
    const float* gn2_b     = (const float*)d_in[10];
    const float* W1a       = (const float*)d_in[11];
    const float* b1a       = (const float*)d_in[12];
    const float* W2a       = (const float*)d_in[13];
    const float* b2a       = (const float*)d_in[14];
    const float* W1b       = (const float*)d_in[15];
    const float* b1b       = (const float*)d_in[16];
    const float* W2b       = (const float*)d_in[17];
    const float* b2b       = (const float*)d_in[18];
    float* out = (float*)d_out;

    int n_edges  = in_sizes[0] / 64;
    int n_angles = in_sizes[1] / 40;

    k_zero<<<512, 256>>>(n_edges);
    k_bounds<<<1, 256>>>(ca, ce, n_angles, n_edges);
    dim3 g1(1024, 2);
    k_precompute<<<g1, 128>>>(nbr, W_full, n_edges);
    k_count<<<(n_angles + 255) / 256, 256>>>(anb, n_angles);
    k_scanA<<<SCAN_BLOCKS, 256>>>(n_edges);
    k_scanB<<<1, SCAN_BLOCKS>>>(n_edges);
    k_scanC<<<SCAN_BLOCKS, 256>>>(n_edges);
    k_fill<<<(n_angles + 255) / 256, 256>>>(anb, ca, n_angles);
    int nblk = 4096;
    int chunk = ((n_angles + nblk - 1) / nblk + ATILE - 1) / ATILE * ATILE;
    k_angle_mma<<<nblk, 128>>>(angle_fea, anb, ca, W_full, n_angles, chunk);
    k_stats1<<<256, 128>>>(gn1_g, gn1_b);
    k_gather<<<2048, 256>>>(ce, W_mask, n_edges);
    k_stats2<<<256, 64>>>(gn2_g, gn2_b);
    k_final<<<(n_edges + 255) / 256, 256>>>(nbr, ce, W1a, b1a, W2a, b2a,
                                            W1b, b1b, W2b, b2b, out, n_edges);
}

// round 14
// speedup vs baseline: 1.5909x; 1.2725x over previous
#include <cuda_runtime.h>
#include <cuda_fp16.h>
#include <math.h>

#define NE_MAX 200000
#define NA_MAX 1600000
#define ATILE 32
#define SCAN_BLOCKS 256
#define SP_STRIDE 136

// ---- static scratch ----
__device__ __half g_P0h[(size_t)NE_MAX * 128];
__device__ __half g_P1h[(size_t)NE_MAX * 128];
__device__ __half g_gbufh[(size_t)NA_MAX * 128];
__device__ float g_csum[256 * 128];
__device__ float g_csumsq[256 * 128];
__device__ int g_cbound[257];
__device__ int g_ebound[257];
__device__ float g_a1[256 * 128];
__device__ float g_b1[256 * 128];
__device__ float g_summed[(size_t)NE_MAX * 64];
__device__ unsigned g_acnt[NE_MAX];
__device__ unsigned g_off[NE_MAX + 1];
__device__ unsigned g_curs[NE_MAX];
__device__ unsigned g_bucket[NA_MAX];   // aid | (crystal << 24)
__device__ unsigned g_blksum[SCAN_BLOCKS];
__device__ unsigned g_blkoff[SCAN_BLOCKS];
__device__ float g_esum[256 * 64];
__device__ float g_esumsq[256 * 64];
__device__ float g_a2[256 * 64];
__device__ float g_b2[256 * 64];

typedef unsigned long long ull;
__device__ __forceinline__ ull ffma2(ull a, ull b, ull c) {
    ull d; asm("fma.rn.f32x2 %0, %1, %2, %3;" : "=l"(d) : "l"(a), "l"(b), "l"(c)); return d;
}
__device__ __forceinline__ ull addf2(ull a, ull b) {
    ull d; asm("add.rn.f32x2 %0, %1, %2;" : "=l"(d) : "l"(a), "l"(b)); return d;
}
__device__ __forceinline__ ull pack2(float x, float y) {
    ull d; asm("mov.b64 %0, {%1, %2};" : "=l"(d) : "f"(x), "f"(y)); return d;
}
__device__ __forceinline__ float2 unpack2(ull a) {
    float x, y; asm("mov.b64 {%0, %1}, %2;" : "=f"(x), "=f"(y) : "l"(a));
    return make_float2(x, y);
}
__device__ __forceinline__ float4 ld_half4(const __half* p) {
    uint2 u = *(const uint2*)p;
    float2 fa = __half22float2(*(__half2*)&u.x);
    float2 fb = __half22float2(*(__half2*)&u.y);
    return make_float4(fa.x, fa.y, fb.x, fb.y);
}
__device__ __forceinline__ void cp_async8(void* smem, const void* gmem) {
    unsigned s = (unsigned)__cvta_generic_to_shared(smem);
    asm volatile("cp.async.ca.shared.global [%0], [%1], 8;" :: "r"(s), "l"(gmem));
}
__device__ __forceinline__ void cp_async16(void* smem, const void* gmem) {
    unsigned s = (unsigned)__cvta_generic_to_shared(smem);
    asm volatile("cp.async.cg.shared.global [%0], [%1], 16;" :: "r"(s), "l"(gmem));
}
__device__ __forceinline__ void cp_async4(void* smem, const void* gmem) {
    unsigned s = (unsigned)__cvta_generic_to_shared(smem);
    asm volatile("cp.async.ca.shared.global [%0], [%1], 4;" :: "r"(s), "l"(gmem));
}
__device__ __forceinline__ void cp_commit() { asm volatile("cp.async.commit_group;" ::: "memory"); }
template <int N>
__device__ __forceinline__ void cp_wait() { asm volatile("cp.async.wait_group %0;" :: "n"(N) : "memory"); }
__device__ __forceinline__ void mma_16816(float c[4], unsigned a0, unsigned a1,
                                          unsigned a2, unsigned a3,
                                          unsigned b0, unsigned b1) {
    asm volatile(
        "mma.sync.aligned.m16n8k16.row.col.f32.f16.f16.f32 "
        "{%0,%1,%2,%3}, {%4,%5,%6,%7}, {%8,%9}, {%0,%1,%2,%3};"
        : "+f"(c[0]), "+f"(c[1]), "+f"(c[2]), "+f"(c[3])
        : "r"(a0), "r"(a1), "r"(a2), "r"(a3), "r"(b0), "r"(b1));
}

// ---- K0: zero accumulators ----
__global__ void k_zero(int n_edges) {
    int i = blockIdx.x * blockDim.x + threadIdx.x;
    int stride = gridDim.x * blockDim.x;
    for (int k = i; k < n_edges; k += stride) g_acnt[k] = 0u;
    for (int k = i; k < 256 * 128; k += stride) { g_csum[k] = 0.f; g_csumsq[k] = 0.f; }
    for (int k = i; k < 256 * 64; k += stride) { g_esum[k] = 0.f; g_esumsq[k] = 0.f; }
}

// ---- K0b: per-crystal segment bounds via binary search ----
__global__ void k_bounds(const int* __restrict__ ca, const int* __restrict__ ce,
                         int n_angles, int n_edges) {
    int c = threadIdx.x;
    int lo = 0, hi = n_angles;
    while (lo < hi) { int mid = (lo + hi) >> 1; if (__ldg(&ca[mid]) < c) lo = mid + 1; else hi = mid; }
    g_cbound[c] = lo;
    lo = 0; hi = n_edges;
    while (lo < hi) { int mid = (lo + hi) >> 1; if (__ldg(&ce[mid]) < c) lo = mid + 1; else hi = mid; }
    g_ebound[c] = lo;
    if (c == 0) { g_cbound[256] = n_angles; g_ebound[256] = n_edges; }
}

// ---- K1: P0/P1 via HMMA. 32-edge tiles, K=64 (4 k-steps), blockIdx.y = half. ----
__global__ void __launch_bounds__(128) k_pre_mma(
        const float* __restrict__ nbr, const float* __restrict__ W_full,
        int n_edges, int chunk) {
    int tid = threadIdx.x;
    int wid = tid >> 5, lane = tid & 31;
    int g = lane >> 2, t = lane & 3;
    int nbase = wid * 32;
    int half = blockIdx.y;
    __half* P = half ? g_P1h : g_P0h;
    const float* wb = W_full + (size_t)(40 + half * 64) * 128;

    unsigned bfrag[4][4][2];
#pragma unroll
    for (int nt = 0; nt < 4; nt++)
#pragma unroll
        for (int ks = 0; ks < 4; ks++) {
            int ch = nbase + nt * 8 + g;
            int k0 = ks * 16 + 2 * t;
            __half2 h0 = __floats2half2_rn(__ldg(&wb[(size_t)k0 * 128 + ch]),
                                           __ldg(&wb[(size_t)(k0 + 1) * 128 + ch]));
            __half2 h1 = __floats2half2_rn(__ldg(&wb[(size_t)(k0 + 8) * 128 + ch]),
                                           __ldg(&wb[(size_t)(k0 + 9) * 128 + ch]));
            bfrag[nt][ks][0] = *(unsigned*)&h0;
            bfrag[nt][ks][1] = *(unsigned*)&h1;
        }

    __shared__ __align__(16) float s_nb[2][ATILE * 64];
    __shared__ __align__(16) __half sAh[32][72];

    int tile0 = blockIdx.x * chunk;
    int tend = min(tile0 + chunk, (n_edges + ATILE - 1) / ATILE);
    if (tile0 >= tend) return;
    int maxf4 = n_edges * 16 - 1;   // float4 index bound

    {
#pragma unroll
        for (int q = 0; q < 4; q++) {
            int pos = q * 128 + tid;   // float4 units, 512 per tile
            cp_async16(&((float4*)s_nb[0])[pos],
                       &((const float4*)nbr)[min(tile0 * 512 + pos, maxf4)]);
        }
        cp_commit();
    }

    int buf = 0;
    for (int tile = tile0; tile < tend; tile++, buf ^= 1) {
        bool has_next = tile + 1 < tend;
        if (has_next) {
#pragma unroll
            for (int q = 0; q < 4; q++) {
                int pos = q * 128 + tid;
                cp_async16(&((float4*)s_nb[buf ^ 1])[pos],
                           &((const float4*)nbr)[min((tile + 1) * 512 + pos, maxf4)]);
            }
            cp_commit();
            cp_wait<1>();
        } else {
            cp_wait<0>();
        }
        __syncthreads();
        const float* nv = s_nb[buf];
#pragma unroll
        for (int q = 0; q < 16; q++) {
            int idx = q * 128 + tid;
            sAh[idx >> 6][idx & 63] = __float2half_rn(nv[idx]);
        }
        __syncthreads();

        int e0 = tile * ATILE;
#pragma unroll
        for (int mt = 0; mt < 2; mt++) {
            int rA = mt * 16 + g;
            int rB = rA + 8;
            float c[4][4];
#pragma unroll
            for (int nt = 0; nt < 4; nt++)
#pragma unroll
                for (int q = 0; q < 4; q++) c[nt][q] = 0.f;
#pragma unroll
            for (int ks = 0; ks < 4; ks++) {
                unsigned a0f = *(const unsigned*)&sAh[rA][ks * 16 + 2 * t];
                unsigned a1f = *(const unsigned*)&sAh[rB][ks * 16 + 2 * t];
                unsigned a2f = *(const unsigned*)&sAh[rA][ks * 16 + 2 * t + 8];
                unsigned a3f = *(const unsigned*)&sAh[rB][ks * 16 + 2 * t + 8];
#pragma unroll
                for (int nt = 0; nt < 4; nt++)
                    mma_16816(c[nt], a0f, a1f, a2f, a3f,
                              bfrag[nt][ks][0], bfrag[nt][ks][1]);
            }
            int eA = e0 + rA, eB = e0 + rB;
#pragma unroll
            for (int nt = 0; nt < 4; nt++) {
                int ch = nbase + nt * 8 + 2 * t;
                if (eA < n_edges)
                    *(__half2*)&P[(size_t)eA * 128 + ch] = __floats2half2_rn(c[nt][0], c[nt][1]);
                if (eB < n_edges)
                    *(__half2*)&P[(size_t)eB * 128 + ch] = __floats2half2_rn(c[nt][2], c[nt][3]);
            }
        }
        __syncthreads();
    }
}

// ---- K2: count angles per src edge ----
__global__ void k_count(const int* __restrict__ anb, int n_angles) {
    int i = blockIdx.x * blockDim.x + threadIdx.x;
    if (i < n_angles) atomicAdd(&g_acnt[anb[2 * (size_t)i]], 1u);
}

// ---- K3: angle GEMM via HMMA; smem-staged P; register-resident norm1 stats ----
__global__ void __launch_bounds__(128) k_angle_mma(
        const float* __restrict__ af, const int* __restrict__ anb,
        const int* __restrict__ ca, const float* __restrict__ W,
        int n_angles, int chunk) {
    int tid = threadIdx.x;
    int wid = tid >> 5, lane = tid & 31;
    int g = lane >> 2, t = lane & 3;
    int nbase = wid * 32;

    unsigned bfrag[4][3][2];
#pragma unroll
    for (int nt = 0; nt < 4; nt++)
#pragma unroll
        for (int ks = 0; ks < 3; ks++) {
            int ch = nbase + nt * 8 + g;
            int k0 = ks * 16 + 2 * t;
            float w00 = (k0 < 40)     ? __ldg(&W[(size_t)k0 * 128 + ch]) : 0.f;
            float w01 = (k0 + 1 < 40) ? __ldg(&W[(size_t)(k0 + 1) * 128 + ch]) : 0.f;
            float w10 = (k0 + 8 < 40) ? __ldg(&W[(size_t)(k0 + 8) * 128 + ch]) : 0.f;
            float w11 = (k0 + 9 < 40) ? __ldg(&W[(size_t)(k0 + 9) * 128 + ch]) : 0.f;
            __half2 h0 = __floats2half2_rn(w00, w01);
            __half2 h1 = __floats2half2_rn(w10, w11);
            bfrag[nt][ks][0] = *(unsigned*)&h0;
            bfrag[nt][ks][1] = *(unsigned*)&h1;
        }

    __shared__ __align__(16) ull s_af[2][ATILE * 20];
    __shared__ int s_ii[2][ATILE * 2];
    __shared__ int s_ca[2][ATILE];
    __shared__ __align__(16) __half sAh[32][56];
    __shared__ __align__(16) __half sP[64][SP_STRIDE];

    for (int idx = tid; idx < 32 * 16; idx += 128)
        sAh[idx >> 4][40 + (idx & 15)] = __float2half(0.f);

    int a0 = blockIdx.x * chunk;
    int aend = min(a0 + chunk, n_angles);
    if (a0 >= aend) return;

    const ull* af2 = (const ull*)af;
    int maxf2 = n_angles * 20 - 1;
    int maxi  = n_angles - 1;

    {
#pragma unroll
        for (int r = 0; r < 5; r++) {
            int pos = r * 128 + tid;
            cp_async8(&s_af[0][pos], &af2[min(a0 * 20 + pos, maxf2)]);
        }
        if (tid < 64) cp_async4(&s_ii[0][tid], &anb[min(2 * a0 + tid, 2 * maxi + 1)]);
        else if (tid < 96) cp_async4(&s_ca[0][tid - 64], &ca[min(a0 + tid - 64, maxi)]);
        cp_commit();
    }

    ull zsum[4] = {0ull, 0ull, 0ull, 0ull};
    ull zsq[4]  = {0ull, 0ull, 0ull, 0ull};
    int curc = -1;

    int buf = 0;
    for (int base = a0; base < aend; base += ATILE, buf ^= 1) {
        int nbase2 = base + ATILE;
        bool has_next = nbase2 < aend;
        cp_wait<0>();
        __syncthreads();

#pragma unroll
        for (int q = 0; q < 8; q++) {
            int cidx = q * 128 + tid;
            int row = cidx >> 4;
            int off = (cidx & 15) * 8;
            int idx = (row < 32) ? s_ii[buf][2 * row] : s_ii[buf][2 * (row - 32) + 1];
            const __half* src = (row < 32) ? &g_P0h[(size_t)idx * 128 + off]
                                           : &g_P1h[(size_t)idx * 128 + off];
            cp_async16(&sP[row][off], src);
        }
        cp_commit();

        if (has_next) {
#pragma unroll
            for (int r = 0; r < 5; r++) {
                int pos = r * 128 + tid;
                cp_async8(&s_af[buf ^ 1][pos], &af2[min(nbase2 * 20 + pos, maxf2)]);
            }
            if (tid < 64) cp_async4(&s_ii[buf ^ 1][tid], &anb[min(2 * nbase2 + tid, 2 * maxi + 1)]);
            else if (tid < 96) cp_async4(&s_ca[buf ^ 1][tid - 64], &ca[min(nbase2 + tid - 64, maxi)]);
            cp_commit();
        }

        const float* afv = (const float*)s_af[buf];
#pragma unroll
        for (int q = 0; q < 10; q++) {
            int idx = q * 128 + tid;
            sAh[idx / 40][idx % 40] = __float2half_rn(afv[idx]);
        }
        if (has_next) cp_wait<1>(); else cp_wait<0>();
        __syncthreads();

#pragma unroll
        for (int mt = 0; mt < 2; mt++) {
            int rA = mt * 16 + g;
            int rB = rA + 8;
            float c[4][4];
#pragma unroll
            for (int nt = 0; nt < 4; nt++)
#pragma unroll
                for (int q = 0; q < 4; q++) c[nt][q] = 0.f;
#pragma unroll
            for (int ks = 0; ks < 3; ks++) {
                unsigned a0f = *(const unsigned*)&sAh[rA][ks * 16 + 2 * t];
                unsigned a1f = *(const unsigned*)&sAh[rB][ks * 16 + 2 * t];
                unsigned a2f = *(const unsigned*)&sAh[rA][ks * 16 + 2 * t + 8];
                unsigned a3f = *(const unsigned*)&sAh[rB][ks * 16 + 2 * t + 8];
#pragma unroll
                for (int nt = 0; nt < 4; nt++)
                    mma_16816(c[nt], a0f, a1f, a2f, a3f,
                              bfrag[nt][ks][0], bfrag[nt][ks][1]);
            }
            int angleA = base + rA;
            int angleB = base + rB;
            ull xpA[4], xpB[4];
#pragma unroll
            for (int nt = 0; nt < 4; nt++) {
                int ch = nbase + nt * 8 + 2 * t;
                float2 q0A = __half22float2(*(const __half2*)&sP[rA][ch]);
                float2 q1A = __half22float2(*(const __half2*)&sP[32 + rA][ch]);
                float xA0 = c[nt][0] + q0A.x + q1A.x;
                float xA1 = c[nt][1] + q0A.y + q1A.y;
                xpA[nt] = pack2(xA0, xA1);
                float2 q0B = __half22float2(*(const __half2*)&sP[rB][ch]);
                float2 q1B = __half22float2(*(const __half2*)&sP[32 + rB][ch]);
                float xB0 = c[nt][2] + q0B.x + q1B.x;
                float xB1 = c[nt][3] + q0B.y + q1B.y;
                xpB[nt] = pack2(xB0, xB1);
                if (angleA < aend)
                    *(__half2*)&g_gbufh[(size_t)angleA * 128 + ch] = __floats2half2_rn(xA0, xA1);
                if (angleB < aend)
                    *(__half2*)&g_gbufh[(size_t)angleB * 128 + ch] = __floats2half2_rn(xB0, xB1);
            }
            if (angleA < aend) {
                int cA = s_ca[buf][rA];
                if (cA != curc) {
                    if (curc >= 0) {
#pragma unroll
                        for (int nt = 0; nt < 4; nt++) {
                            int ch = nbase + nt * 8 + 2 * t;
                            float2 us = unpack2(zsum[nt]), uq = unpack2(zsq[nt]);
                            atomicAdd(&g_csum[curc * 128 + ch], us.x);
                            atomicAdd(&g_csum[curc * 128 + ch + 1], us.y);
                            atomicAdd(&g_csumsq[curc * 128 + ch], uq.x);
                            atomicAdd(&g_csumsq[curc * 128 + ch + 1], uq.y);
                            zsum[nt] = 0ull; zsq[nt] = 0ull;
                        }
                    }
                    curc = cA;
                }
#pragma unroll
                for (int nt = 0; nt < 4; nt++) {
                    zsum[nt] = addf2(zsum[nt], xpA[nt]);
                    zsq[nt] = ffma2(xpA[nt], xpA[nt], zsq[nt]);
                }
            }
            if (angleB < aend) {
                int cB = s_ca[buf][rB];
                if (cB != curc) {
                    if (curc >= 0) {
#pragma unroll
                        for (int nt = 0; nt < 4; nt++) {
                            int ch = nbase + nt * 8 + 2 * t;
                            float2 us = unpack2(zsum[nt]), uq = unpack2(zsq[nt]);
                            atomicAdd(&g_csum[curc * 128 + ch], us.x);
                            atomicAdd(&g_csum[curc * 128 + ch + 1], us.y);
                            atomicAdd(&g_csumsq[curc * 128 + ch], uq.x);
                            atomicAdd(&g_csumsq[curc * 128 + ch + 1], uq.y);
                            zsum[nt] = 0ull; zsq[nt] = 0ull;
                        }
                    }
                    curc = cB;
                }
#pragma unroll
                for (int nt = 0; nt < 4; nt++) {
                    zsum[nt] = addf2(zsum[nt], xpB[nt]);
                    zsq[nt] = ffma2(xpB[nt], xpB[nt], zsq[nt]);
                }
            }
        }
        __syncthreads();
    }
    if (curc >= 0) {
#pragma unroll
        for (int nt = 0; nt < 4; nt++) {
            int ch = nbase + nt * 8 + 2 * t;
            float2 us = unpack2(zsum[nt]), uq = unpack2(zsq[nt]);
            atomicAdd(&g_csum[curc * 128 + ch], us.x);
            atomicAdd(&g_csum[curc * 128 + ch + 1], us.y);
            atomicAdd(&g_csumsq[curc * 128 + ch], uq.x);
            atomicAdd(&g_csumsq[curc * 128 + ch + 1], uq.y);
        }
    }
}

// ---- K4: finalize crystal_norm1 affine ----
__global__ void k_stats1(const float* __restrict__ gn1_g, const float* __restrict__ gn1_b) {
    int c = blockIdx.x, j = threadIdx.x;
    float cnt = fmaxf((float)(g_cbound[c + 1] - g_cbound[c]), 1.f);
    float mean = g_csum[c * 128 + j] / cnt;
    float var = fmaxf(g_csumsq[c * 128 + j] / cnt - mean * mean, 0.f);
    float inv = rsqrtf(var + 1e-5f);
    float a = gn1_g[j] * inv;
    g_a1[c * 128 + j] = a;
    g_b1[c * 128 + j] = gn1_b[j] - mean * a;
}

// ---- K5a/b/c: parallel exclusive scan over counts ----
__global__ void k_scanA(int n_edges) {
    __shared__ unsigned sred[256];
    int b = blockIdx.x, t = threadIdx.x;
    int per = (n_edges + SCAN_BLOCKS - 1) / SCAN_BLOCKS;
    int s = b * per, e = min(s + per, n_edges);
    unsigned local = 0;
    for (int i = s + t; i < e; i += 256) local += g_acnt[i];
    sred[t] = local;
    __syncthreads();
    for (int off = 128; off; off >>= 1) {
        if (t < off) sred[t] += sred[t + off];
        __syncthreads();
    }
    if (t == 0) g_blksum[b] = sred[0];
}
__global__ void k_scanB(int n_edges) {
    __shared__ unsigned ss[SCAN_BLOCKS];
    int t = threadIdx.x;
    ss[t] = g_blksum[t];
    __syncthreads();
    for (int off = 1; off < SCAN_BLOCKS; off <<= 1) {
        unsigned v = (t >= off) ? ss[t - off] : 0u;
        __syncthreads();
        if (t >= off) ss[t] += v;
        __syncthreads();
    }
    g_blkoff[t] = ss[t] - g_blksum[t];
    if (t == SCAN_BLOCKS - 1) g_off[n_edges] = ss[t];
}
__global__ void k_scanC(int n_edges) {
    __shared__ unsigned ss[256];
    int b = blockIdx.x, t = threadIdx.x;
    int per = (n_edges + SCAN_BLOCKS - 1) / SCAN_BLOCKS;
    int s0 = b * per, e0 = min(s0 + per, n_edges);
    int per2 = (per + 255) / 256;
    int s = s0 + t * per2, e = min(s + per2, e0);
    unsigned local = 0;
    for (int i = s; i < e; i++) local += g_acnt[i];
    ss[t] = local;
    __syncthreads();
    for (int off = 1; off < 256; off <<= 1) {
        unsigned v = (t >= off) ? ss[t - off] : 0u;
        __syncthreads();
        if (t >= off) ss[t] += v;
        __syncthreads();
    }
    unsigned run = g_blkoff[b] + ss[t] - local;
    for (int i = s; i < e; i++) {
        unsigned c = g_acnt[i];
        g_off[i] = run;
        g_curs[i] = run;
        run += c;
    }
}

// ---- K6: fill CSR buckets, crystal id packed into high bits ----
__global__ void k_fill(const int* __restrict__ anb, const int* __restrict__ ca,
                       int n_angles) {
    int i = blockIdx.x * blockDim.x + threadIdx.x;
    if (i < n_angles) {
        int s = anb[2 * (size_t)i];
        unsigned p = atomicAdd(&g_curs[s], 1u);
        g_bucket[p] = (unsigned)i | ((unsigned)ca[i] << 24);
    }
}

// ---- K7: fused gate+gather, packed-bucket ----
__global__ void __launch_bounds__(256) k_gather(const int* __restrict__ ce,
                                                const float* __restrict__ W_mask,
                                                int n_edges) {
    int gw = blockIdx.x * (blockDim.x >> 5) + (threadIdx.x >> 5);
    int lane = threadIdx.x & 31;
    int totalw = gridDim.x * (blockDim.x >> 5);
    int chunk = (n_edges + totalw - 1) / totalw;
    int e0 = gw * chunk, eend = min(e0 + chunk, n_edges);
    if (e0 >= eend) return;
    float4 wm = make_float4(0.f, 0.f, 0.f, 0.f);
    if (lane >= 16) wm = ((const float4*)W_mask)[lane - 16];
    float4 lsum = make_float4(0.f, 0.f, 0.f, 0.f);
    float4 lsq  = make_float4(0.f, 0.f, 0.f, 0.f);
    int curc = __ldg(&ce[e0]);
    for (int e = e0; e < eend; e++) {
        int c = __ldg(&ce[e]);
        if (c != curc) {
            if (lane < 16) {
                int b = curc * 64 + 4 * lane;
                atomicAdd(&g_esum[b + 0], lsum.x); atomicAdd(&g_esum[b + 1], lsum.y);
                atomicAdd(&g_esum[b + 2], lsum.z); atomicAdd(&g_esum[b + 3], lsum.w);
                atomicAdd(&g_esumsq[b + 0], lsq.x); atomicAdd(&g_esumsq[b + 1], lsq.y);
                atomicAdd(&g_esumsq[b + 2], lsq.z); atomicAdd(&g_esumsq[b + 3], lsq.w);
            }
            lsum = make_float4(0.f, 0.f, 0.f, 0.f);
            lsq = make_float4(0.f, 0.f, 0.f, 0.f);
            curc = c;
        }
        unsigned s = g_off[e], t = g_off[e + 1];
        float4 acc = make_float4(0.f, 0.f, 0.f, 0.f);
        for (unsigned p = s; p < t; p += 2) {
            bool two = (p + 1 < t);
            unsigned vA = __ldg(&g_bucket[p]);
            unsigned vB = two ? __ldg(&g_bucket[p + 1]) : vA;
            int aidA = vA & 0xFFFFFFu, ccA = vA >> 24;
            int aidB = vB & 0xFFFFFFu, ccB = vB >> 24;
            float4 gA = ld_half4(&g_gbufh[(size_t)aidA * 128 + 4 * lane]);
            float4 gB = ld_half4(&g_gbufh[(size_t)aidB * 128 + 4 * lane]);
            float4 aA = *(const float4*)&g_a1[ccA * 128 + 4 * lane];
            float4 bA = *(const float4*)&g_b1[ccA * 128 + 4 * lane];
            float4 aB = *(const float4*)&g_a1[ccB * 128 + 4 * lane];
            float4 bB = *(const float4*)&g_b1[ccB * 128 + 4 * lane];
            float xA0 = fmaf(gA.x, aA.x, bA.x), xA1 = fmaf(gA.y, aA.y, bA.y);
            float xA2 = fmaf(gA.z, aA.z, bA.z), xA3 = fmaf(gA.w, aA.w, bA.w);
            float xB0 = fmaf(gB.x, aB.x, bB.x), xB1 = fmaf(gB.y, aB.y, bB.y);
            float xB2 = fmaf(gB.z, aB.z, bB.z), xB3 = fmaf(gB.w, aB.w, bB.w);
            float pA = xA0 * wm.x + xA1 * wm.y + xA2 * wm.z + xA3 * wm.w;
            float pB = xB0 * wm.x + xB1 * wm.y + xB2 * wm.z + xB3 * wm.w;
#pragma unroll
            for (int o = 16; o; o >>= 1) {
                pA += __shfl_xor_sync(0xffffffffu, pA, o);
                pB += __shfl_xor_sync(0xffffffffu, pB, o);
            }
            float fA = 1.f - 2.f / (__expf(2.f * pA) + 1.f);
            float fB = 1.f - 2.f / (__expf(2.f * pB) + 1.f);
            acc.x += fA * fmaxf(xA0, 0.f);
            acc.y += fA * fmaxf(xA1, 0.f);
            acc.z += fA * fmaxf(xA2, 0.f);
            acc.w += fA * fmaxf(xA3, 0.f);
            if (two) {
                acc.x += fB * fmaxf(xB0, 0.f);
                acc.y += fB * fmaxf(xB1, 0.f);
                acc.z += fB * fmaxf(xB2, 0.f);
                acc.w += fB * fmaxf(xB3, 0.f);
            }
        }
        float inv = 1.f / fmaxf((float)(t - s), 1.f);
        float4 v = make_float4(acc.x * inv, acc.y * inv, acc.z * inv, acc.w * inv);
        if (lane < 16) {
            *(float4*)&g_summed[(size_t)e * 64 + 4 * lane] = v;
            lsum.x += v.x; lsum.y += v.y; lsum.z += v.z; lsum.w += v.w;
            lsq.x += v.x * v.x; lsq.y += v.y * v.y; lsq.z += v.z * v.z; lsq.w += v.w * v.w;
        }
    }
    if (lane < 16) {
        int b = curc * 64 + 4 * lane;
        atomicAdd(&g_esum[b + 0], lsum.x); atomicAdd(&g_esum[b + 1], lsum.y);
        atomicAdd(&g_esum[b + 2], lsum.z); atomicAdd(&g_esum[b + 3], lsum.w);
        atomicAdd(&g_esumsq[b + 0], lsq.x); atomicAdd(&g_esumsq[b + 1], lsq.y);
        atomicAdd(&g_esumsq[b + 2], lsq.z); atomicAdd(&g_esumsq[b + 3], lsq.w);
    }
}

// ---- K9: finalize crystal_norm2 affine ----
__global__ void k_stats2(const float* __restrict__ gn2_g, const float* __restrict__ gn2_b) {
    int c = blockIdx.x, j = threadIdx.x;
    float cnt = fmaxf((float)(g_ebound[c + 1] - g_ebound[c]), 1.f);
    float mean = g_esum[c * 64 + j] / cnt;
    float var = fmaxf(g_esumsq[c * 64 + j] / cnt - mean * mean, 0.f);
    float inv = rsqrtf(var + 1e-5f);
    float a = gn2_g[j] * inv;
    g_a2[c * 64 + j] = a;
    g_b2[c * 64 + j] = gn2_b[j] - mean * a;
}

// ---- K10: thread-per-edge residual MLPs ----
__global__ void __launch_bounds__(256) k_final(
        const float* __restrict__ nbr, const int* __restrict__ ce,
        const float* __restrict__ W1a, const float* __restrict__ b1a,
        const float* __restrict__ W2a, const float* __restrict__ b2a,
        const float* __restrict__ W1b, const float* __restrict__ b1b,
        const float* __restrict__ W2b, const float* __restrict__ b2b,
        float* __restrict__ out, int n_edges) {
    __shared__ float4 sW1a[512], sW2a[512], sW1b[512], sW2b[512];
    __shared__ float sb1a[32], sb2a[64], sb1b[32], sb2b[64];
    int t = threadIdx.x;
    for (int k = t; k < 512; k += 256) {
        sW1a[k] = ((const float4*)W1a)[k];
        sW2a[k] = ((const float4*)W2a)[k];
        sW1b[k] = ((const float4*)W1b)[k];
        sW2b[k] = ((const float4*)W2b)[k];
    }
    if (t < 32) { sb1a[t] = b1a[t]; sb1b[t] = b1b[t]; }
    if (t < 64) { sb2a[t] = b2a[t]; sb2b[t] = b2b[t]; }
    __syncthreads();
    int e = blockIdx.x * 256 + t;
    if (e >= n_edges) return;

    float h[64];
    int c = __ldg(&ce[e]);
    {
        const float4* s4 = (const float4*)&g_summed[(size_t)e * 64];
        const float4* a4 = (const float4*)&g_a2[c * 64];
        const float4* b4 = (const float4*)&g_b2[c * 64];
#pragma unroll
        for (int i = 0; i < 16; i++) {
            float4 sv = s4[i], av = a4[i], bv = b4[i];
            h[4 * i + 0] = fmaf(sv.x, av.x, bv.x);
            h[4 * i + 1] = fmaf(sv.y, av.y, bv.y);
            h[4 * i + 2] = fmaf(sv.z, av.z, bv.z);
            h[4 * i + 3] = fmaf(sv.w, av.w, bv.w);
        }
    }
    float r[32];
    {
        ull racc[16];
#pragma unroll
        for (int j = 0; j < 16; j++) racc[j] = pack2(sb1a[2 * j], sb1a[2 * j + 1]);
#pragma unroll
        for (int k = 0; k < 64; k++) {
            ull hk = pack2(h[k], h[k]);
#pragma unroll
            for (int j = 0; j < 8; j++) {
                float4 w4 = sW1a[k * 8 + j];
                racc[2 * j]     = ffma2(hk, pack2(w4.x, w4.y), racc[2 * j]);
                racc[2 * j + 1] = ffma2(hk, pack2(w4.z, w4.w), racc[2 * j + 1]);
            }
        }
#pragma unroll
        for (int j = 0; j < 16; j++) {
            float2 u = unpack2(racc[j]);
            r[2 * j] = fmaxf(u.x, 0.f);
            r[2 * j + 1] = fmaxf(u.y, 0.f);
        }
        ull hacc[32];
#pragma unroll
        for (int j = 0; j < 32; j++) hacc[j] = pack2(h[2 * j] + sb2a[2 * j], h[2 * j + 1] + sb2a[2 * j + 1]);
#pragma unroll
        for (int k = 0; k < 32; k++) {
            ull rk = pack2(r[k], r[k]);
#pragma unroll
            for (int j = 0; j < 16; j++) {
                float4 w4 = sW2a[k * 16 + j];
                hacc[2 * j]     = ffma2(rk, pack2(w4.x, w4.y), hacc[2 * j]);
                hacc[2 * j + 1] = ffma2(rk, pack2(w4.z, w4.w), hacc[2 * j + 1]);
            }
        }
#pragma unroll
        for (int j = 0; j < 32; j++) {
            float2 u = unpack2(hacc[j]);
            h[2 * j] = u.x; h[2 * j + 1] = u.y;
        }
    }
    {
        ull racc[16];
#pragma unroll
        for (int j = 0; j < 16; j++) racc[j] = pack2(sb1b[2 * j], sb1b[2 * j + 1]);
#pragma unroll
        for (int k = 0; k < 64; k++) {
            ull hk = pack2(h[k], h[k]);
#pragma unroll
            for (int j = 0; j < 8; j++) {
                float4 w4 = sW1b[k * 8 + j];
                racc[2 * j]     = ffma2(hk, pack2(w4.x, w4.y), racc[2 * j]);
                racc[2 * j + 1] = ffma2(hk, pack2(w4.z, w4.w), racc[2 * j + 1]);
            }
        }
#pragma unroll
        for (int j = 0; j < 16; j++) {
            float2 u = unpack2(racc[j]);
            r[2 * j] = fmaxf(u.x, 0.f);
            r[2 * j + 1] = fmaxf(u.y, 0.f);
        }
        ull hacc[32];
#pragma unroll
        for (int j = 0; j < 32; j++) hacc[j] = pack2(h[2 * j] + sb2b[2 * j], h[2 * j + 1] + sb2b[2 * j + 1]);
#pragma unroll
        for (int k = 0; k < 32; k++) {
            ull rk = pack2(r[k], r[k]);
#pragma unroll
            for (int j = 0; j < 16; j++) {
                float4 w4 = sW2b[k * 16 + j];
                hacc[2 * j]     = ffma2(rk, pack2(w4.x, w4.y), hacc[2 * j]);
                hacc[2 * j + 1] = ffma2(rk, pack2(w4.z, w4.w), hacc[2 * j + 1]);
            }
        }
#pragma unroll
        for (int j = 0; j < 32; j++) {
            float2 u = unpack2(hacc[j]);
            h[2 * j] = u.x; h[2 * j + 1] = u.y;
        }
    }
    {
        const float4* n4 = (const float4*)&nbr[(size_t)e * 64];
        float4* o4 = (float4*)&out[(size_t)e * 64];
#pragma unroll
        for (int i = 0; i < 16; i++) {
            float4 nv = n4[i];
            float4 ov;
            ov.x = 0.7071067811865476f * fmaxf(nv.x + h[4 * i + 0], 0.f);
            ov.y = 0.7071067811865476f * fmaxf(nv.y + h[4 * i + 1], 0.f);
            ov.z = 0.7071067811865476f * fmaxf(nv.z + h[4 * i + 2], 0.f);
            ov.w = 0.7071067811865476f * fmaxf(nv.w + h[4 * i + 3], 0.f);
            o4[i] = ov;
        }
    }
}

extern "C" void kernel_launch(void* const* d_in, const int* in_sizes, int n_in,
                              void* d_out, int out_size) {
    const float* nbr       = (const float*)d_in[0];
    const float* angle_fea = (const float*)d_in[1];
    const int*   anb       = (const int*)d_in[2];
    const int*   ce        = (const int*)d_in[3];
    const int*   ca        = (const int*)d_in[4];
    const float* W_full    = (const float*)d_in[5];
    const float* W_mask    = (const float*)d_in[6];
    const float* gn1_g     = (const float*)d_in[7];
    const float* gn1_b     = (const float*)d_in[8];
    const float* gn2_g     = (const float*)d_in[9];
    const float* gn2_b     = (const float*)d_in[10];
    const float* W1a       = (const float*)d_in[11];
    const float* b1a       = (const float*)d_in[12];
    const float* W2a       = (const float*)d_in[13];
    const float* b2a       = (const float*)d_in[14];
    const float* W1b       = (const float*)d_in[15];
    const float* b1b       = (const float*)d_in[16];
    const float* W2b       = (const float*)d_in[17];
    const float* b2b       = (const float*)d_in[18];
    float* out = (float*)d_out;

    int n_edges  = in_sizes[0] / 64;
    int n_angles = in_sizes[1] / 40;

    k_zero<<<512, 256>>>(n_edges);
    k_bounds<<<1, 256>>>(ca, ce, n_angles, n_edges);
    int ntiles = (n_edges + ATILE - 1) / ATILE;
    int pblk = 1024;
    int pchunk = (ntiles + pblk - 1) / pblk;
    dim3 g1(pblk, 2);
    k_pre_mma<<<g1, 128>>>(nbr, W_full, n_edges, pchunk);
    k_count<<<(n_angles + 255) / 256, 256>>>(anb, n_angles);
    k_scanA<<<SCAN_BLOCKS, 256>>>(n_edges);
    k_scanB<<<1, SCAN_BLOCKS>>>(n_edges);
    k_scanC<<<SCAN_BLOCKS, 256>>>(n_edges);
    k_fill<<<(n_angles + 255) / 256, 256>>>(anb, ca, n_angles);
    int nblk = 4096;
    int chunk = ((n_angles + nblk - 1) / nblk + ATILE - 1) / ATILE * ATILE;
    k_angle_mma<<<nblk, 128>>>(angle_fea, anb, ca, W_full, n_angles, chunk);
    k_stats1<<<256, 128>>>(gn1_g, gn1_b);
    k_gather<<<4096, 256>>>(ce, W_mask, n_edges);
    k_stats2<<<256, 64>>>(gn2_g, gn2_b);
    k_final<<<(n_edges + 255) / 256, 256>>>(nbr, ce, W1a, b1a, W2a, b2a,
                                            W1b, b1b, W2b, b2b, out, n_edges);
}